// round 1
// baseline (speedup 1.0000x reference)
#include <cuda_runtime.h>
#include <math.h>

#define NE      8
#define TOPK    2
#define MTOK    2048
#define KDIM    2048
#define NDIM    1408
#define CAP     1024
#define RROWS   (MTOK * TOPK)

// ---------------- scratch (device globals; no allocations) ----------------
__device__ int   g_counts[NE];
__device__ int   g_tok[NE * CAP];            // expert slot -> token index
__device__ int   g_pos[RROWS];               // routed row  -> slot within expert
__device__ float g_h[(size_t)NE * CAP * NDIM];   // SwiGLU intermediate (E,C,N)  ~46 MB
__device__ float g_d[(size_t)NE * CAP * KDIM];   // down output        (E,C,K)  ~64 MB

// ---------------- routing ----------------
__global__ void route_kernel(const int* __restrict__ idx) {
    __shared__ int scnt[NE];
    int tid = threadIdx.x;
    if (tid < NE) scnt[tid] = 0;
    __syncthreads();
    for (int r = tid; r < RROWS; r += blockDim.x) {
        int e = idx[r];
        int p = atomicAdd(&scnt[e], 1);
        g_pos[r] = p;
        g_tok[e * CAP + p] = r >> 1;  // TOPK == 2
    }
    __syncthreads();
    if (tid < NE) g_counts[tid] = scnt[tid];
}

// ---------------- GEMM1: fused gate+up + SwiGLU ----------------
// C[c,n] over A = gathered tokens (c,K) , B = gate/up weights (N,K); NT dot-of-rows.
#define BM1 128
#define BN1 64
#define BK1 16

__global__ __launch_bounds__(256) void gemm1_kernel(
    const float* __restrict__ X,
    const float* __restrict__ GW,
    const float* __restrict__ UW)
{
    const int e   = blockIdx.z;
    const int cnt = g_counts[e];
    const int c0  = blockIdx.y * BM1;
    if (c0 >= cnt) return;
    const int n0  = blockIdx.x * BN1;

    __shared__ float As[BK1][BM1 + 4];
    __shared__ float Bg[BK1][BN1 + 4];
    __shared__ float Bu[BK1][BN1 + 4];
    __shared__ int   sTok[BM1];

    const int tid = threadIdx.x;

    if (tid < BM1) {
        int c = c0 + tid;
        sTok[tid] = (c < cnt) ? g_tok[e * CAP + c] : g_tok[e * CAP];
    }
    __syncthreads();

    const int arow = tid >> 2;          // 0..63
    const int ak   = (tid & 3) * 4;     // 0,4,8,12
    const float* gwE = GW + (size_t)e * NDIM * KDIM;
    const float* uwE = UW + (size_t)e * NDIM * KDIM;

    const int ty = tid >> 4;            // 0..15 -> rows ty*8..
    const int tx = tid & 15;            // 0..15 -> cols tx*4..

    float accg[8][4];
    float accu[8][4];
#pragma unroll
    for (int i = 0; i < 8; i++)
#pragma unroll
        for (int j = 0; j < 4; j++) { accg[i][j] = 0.f; accu[i][j] = 0.f; }

    for (int kt = 0; kt < KDIM; kt += BK1) {
        // load A tile (128 x 16), gathered
#pragma unroll
        for (int h = 0; h < 2; ++h) {
            int row = arow + h * 64;
            float4 v = *(const float4*)(X + (size_t)sTok[row] * KDIM + kt + ak);
            As[ak + 0][row] = v.x; As[ak + 1][row] = v.y;
            As[ak + 2][row] = v.z; As[ak + 3][row] = v.w;
        }
        // load B tiles (64 x 16) for gate and up
        {
            int n = tid >> 2;  // 0..63
            float4 vg = *(const float4*)(gwE + (size_t)(n0 + n) * KDIM + kt + ak);
            Bg[ak + 0][n] = vg.x; Bg[ak + 1][n] = vg.y;
            Bg[ak + 2][n] = vg.z; Bg[ak + 3][n] = vg.w;
            float4 vu = *(const float4*)(uwE + (size_t)(n0 + n) * KDIM + kt + ak);
            Bu[ak + 0][n] = vu.x; Bu[ak + 1][n] = vu.y;
            Bu[ak + 2][n] = vu.z; Bu[ak + 3][n] = vu.w;
        }
        __syncthreads();

#pragma unroll
        for (int k = 0; k < BK1; ++k) {
            float4 a0 = *(const float4*)&As[k][ty * 8];
            float4 a1 = *(const float4*)&As[k][ty * 8 + 4];
            float4 b0 = *(const float4*)&Bg[k][tx * 4];
            float4 b1 = *(const float4*)&Bu[k][tx * 4];
            float a[8] = {a0.x, a0.y, a0.z, a0.w, a1.x, a1.y, a1.z, a1.w};
            float bg[4] = {b0.x, b0.y, b0.z, b0.w};
            float bu[4] = {b1.x, b1.y, b1.z, b1.w};
#pragma unroll
            for (int i = 0; i < 8; i++) {
#pragma unroll
                for (int j = 0; j < 4; j++) {
                    accg[i][j] = fmaf(a[i], bg[j], accg[i][j]);
                    accu[i][j] = fmaf(a[i], bu[j], accu[i][j]);
                }
            }
        }
        __syncthreads();
    }

    // epilogue: SwiGLU with clamps, write h
#pragma unroll
    for (int i = 0; i < 8; i++) {
        int c = c0 + ty * 8 + i;
        if (c >= cnt) continue;
        float4 out;
        float r[4];
#pragma unroll
        for (int j = 0; j < 4; j++) {
            float g = fminf(accg[i][j], 10.0f);
            float s = g / (1.0f + expf(-g));
            float u = fminf(fmaxf(accu[i][j], -10.0f), 10.0f);
            r[j] = s * u;
        }
        out.x = r[0]; out.y = r[1]; out.z = r[2]; out.w = r[3];
        *(float4*)(g_h + ((size_t)e * CAP + c) * NDIM + n0 + tx * 4) = out;
    }
}

// ---------------- GEMM2: down projection ----------------
// d[c,k] = sum_n h[c,n] * DW[e,k,n]; inner = NDIM.
#define BM2 128
#define BN2 128
#define BK2 16

__global__ __launch_bounds__(256) void gemm2_kernel(const float* __restrict__ DW)
{
    const int e   = blockIdx.z;
    const int cnt = g_counts[e];
    const int c0  = blockIdx.y * BM2;
    if (c0 >= cnt) return;
    const int k0  = blockIdx.x * BN2;

    __shared__ float As[BK2][BM2 + 4];
    __shared__ float Bs[BK2][BN2 + 4];

    const int tid  = threadIdx.x;
    const int arow = tid >> 2;          // 0..63
    const int ak   = (tid & 3) * 4;

    const float* hE  = g_h + (size_t)e * CAP * NDIM;
    const float* dwE = DW  + (size_t)e * KDIM * NDIM;

    const int ty = tid >> 4;
    const int tx = tid & 15;

    float acc[8][8];
#pragma unroll
    for (int i = 0; i < 8; i++)
#pragma unroll
        for (int j = 0; j < 8; j++) acc[i][j] = 0.f;

    for (int nt = 0; nt < NDIM; nt += BK2) {
#pragma unroll
        for (int h = 0; h < 2; ++h) {
            int row = arow + h * 64;
            float4 v = *(const float4*)(hE + (size_t)(c0 + row) * NDIM + nt + ak);
            As[ak + 0][row] = v.x; As[ak + 1][row] = v.y;
            As[ak + 2][row] = v.z; As[ak + 3][row] = v.w;
        }
#pragma unroll
        for (int h = 0; h < 2; ++h) {
            int row = arow + h * 64;
            float4 v = *(const float4*)(dwE + (size_t)(k0 + row) * NDIM + nt + ak);
            Bs[ak + 0][row] = v.x; Bs[ak + 1][row] = v.y;
            Bs[ak + 2][row] = v.z; Bs[ak + 3][row] = v.w;
        }
        __syncthreads();

#pragma unroll
        for (int k = 0; k < BK2; ++k) {
            float4 a0 = *(const float4*)&As[k][ty * 8];
            float4 a1 = *(const float4*)&As[k][ty * 8 + 4];
            float4 b0 = *(const float4*)&Bs[k][tx * 8];
            float4 b1 = *(const float4*)&Bs[k][tx * 8 + 4];
            float a[8] = {a0.x, a0.y, a0.z, a0.w, a1.x, a1.y, a1.z, a1.w};
            float b[8] = {b0.x, b0.y, b0.z, b0.w, b1.x, b1.y, b1.z, b1.w};
#pragma unroll
            for (int i = 0; i < 8; i++)
#pragma unroll
                for (int j = 0; j < 8; j++)
                    acc[i][j] = fmaf(a[i], b[j], acc[i][j]);
        }
        __syncthreads();
    }

#pragma unroll
    for (int i = 0; i < 8; i++) {
        int c = c0 + ty * 8 + i;
        if (c >= cnt) continue;
        float* dst = g_d + ((size_t)e * CAP + c) * KDIM + k0 + tx * 8;
        float4 o0 = {acc[i][0], acc[i][1], acc[i][2], acc[i][3]};
        float4 o1 = {acc[i][4], acc[i][5], acc[i][6], acc[i][7]};
        *(float4*)(dst)     = o0;
        *(float4*)(dst + 4) = o1;
    }
}

// ---------------- combine ----------------
__global__ void combine_kernel(const int* __restrict__ idx,
                               const float* __restrict__ gate,
                               float* __restrict__ out)
{
    const int t = blockIdx.x;
    const int e0 = idx[2 * t], e1 = idx[2 * t + 1];
    const float w0 = gate[2 * t], w1 = gate[2 * t + 1];
    const int p0 = g_pos[2 * t], p1 = g_pos[2 * t + 1];
    const float* d0 = g_d + ((size_t)e0 * CAP + p0) * KDIM;
    const float* d1 = g_d + ((size_t)e1 * CAP + p1) * KDIM;
    float* o = out + (size_t)t * KDIM;

    for (int k = threadIdx.x * 4; k < KDIM; k += blockDim.x * 4) {
        float4 a = *(const float4*)(d0 + k);
        float4 b = *(const float4*)(d1 + k);
        float4 r;
        r.x = w0 * a.x + w1 * b.x;
        r.y = w0 * a.y + w1 * b.y;
        r.z = w0 * a.z + w1 * b.z;
        r.w = w0 * a.w + w1 * b.w;
        *(float4*)(o + k) = r;
    }
}

// ---------------- launch ----------------
extern "C" void kernel_launch(void* const* d_in, const int* in_sizes, int n_in,
                              void* d_out, int out_size)
{
    const float* X    = (const float*)d_in[0];  // flat_h      (M,K)
    const int*   idx  = (const int*)  d_in[1];  // flat_idx    (M,TOPK)
    const float* gate = (const float*)d_in[2];  // flat_gate   (M,TOPK)
    const float* GW   = (const float*)d_in[3];  // gate_weight (E,N,K)
    const float* UW   = (const float*)d_in[4];  // up_weight   (E,N,K)
    const float* DW   = (const float*)d_in[5];  // down_weight (E,K,N)
    float* out = (float*)d_out;

    route_kernel<<<1, 256>>>(idx);

    dim3 g1(NDIM / BN1, CAP / BM1, NE);   // (22, 8, 8)
    gemm1_kernel<<<g1, 256>>>(X, GW, UW);

    dim3 g2(KDIM / BN2, CAP / BM2, NE);   // (16, 8, 8)
    gemm2_kernel<<<g2, 256>>>(DW);

    combine_kernel<<<MTOK, 256>>>(idx, gate, out);
}

// round 3
// speedup vs baseline: 1.9712x; 1.9712x over previous
#include <cuda_runtime.h>
#include <cuda_bf16.h>
#include <math.h>
#include <stdint.h>

#define NE      8
#define TOPK    2
#define MTOK    2048
#define KDIM    2048
#define NDIM    1408
#define CAP     1024
#define RROWS   (MTOK * TOPK)

// ---------------- scratch (device globals; no allocations) ----------------
__device__ int   g_counts[NE];
__device__ int   g_tok[NE * CAP];
__device__ int   g_pos[RROWS];
__device__ __nv_bfloat16 g_a_hi[(size_t)NE * CAP * KDIM];
__device__ __nv_bfloat16 g_a_lo[(size_t)NE * CAP * KDIM];
__device__ __nv_bfloat16 g_gw_hi[(size_t)NE * NDIM * KDIM];
__device__ __nv_bfloat16 g_gw_lo[(size_t)NE * NDIM * KDIM];
__device__ __nv_bfloat16 g_uw_hi[(size_t)NE * NDIM * KDIM];
__device__ __nv_bfloat16 g_uw_lo[(size_t)NE * NDIM * KDIM];
__device__ __nv_bfloat16 g_dw_hi[(size_t)NE * KDIM * NDIM];
__device__ __nv_bfloat16 g_dw_lo[(size_t)NE * KDIM * NDIM];
__device__ __nv_bfloat16 g_h_hi[(size_t)NE * CAP * NDIM];
__device__ __nv_bfloat16 g_h_lo[(size_t)NE * CAP * NDIM];
__device__ float g_d[(size_t)NE * CAP * KDIM];

// ---------------- helpers ----------------
__device__ __forceinline__ uint32_t smem_u32(const void* p) {
    return (uint32_t)__cvta_generic_to_shared(p);
}

#define CPA(dst, src) \
    asm volatile("cp.async.cg.shared.global [%0], [%1], 16;" :: "r"(dst), "l"(src) : "memory")
#define CPC()  asm volatile("cp.async.commit_group;" ::: "memory")
#define CPW1() asm volatile("cp.async.wait_group 1;" ::: "memory")
#define CPW0() asm volatile("cp.async.wait_group 0;" ::: "memory")

__device__ __forceinline__ void ldsm_x4(uint32_t* r, uint32_t a) {
    asm volatile("ldmatrix.sync.aligned.m8n8.x4.shared.b16 {%0,%1,%2,%3}, [%4];"
        : "=r"(r[0]), "=r"(r[1]), "=r"(r[2]), "=r"(r[3]) : "r"(a));
}

__device__ __forceinline__ void mma16816(float* c, const uint32_t* a,
                                         uint32_t b0, uint32_t b1) {
    asm volatile(
        "mma.sync.aligned.m16n8k16.row.col.f32.bf16.bf16.f32 "
        "{%0,%1,%2,%3}, {%4,%5,%6,%7}, {%8,%9}, {%0,%1,%2,%3};"
        : "+f"(c[0]), "+f"(c[1]), "+f"(c[2]), "+f"(c[3])
        : "r"(a[0]), "r"(a[1]), "r"(a[2]), "r"(a[3]), "r"(b0), "r"(b1));
}

__device__ __forceinline__ void split2(float a, float b,
                                       __nv_bfloat162& hi, __nv_bfloat162& lo) {
    __nv_bfloat16 ha = __float2bfloat16(a);
    __nv_bfloat16 hb = __float2bfloat16(b);
    hi.x = ha; hi.y = hb;
    lo.x = __float2bfloat16(a - __bfloat162float(ha));
    lo.y = __float2bfloat16(b - __bfloat162float(hb));
}

// padded tile row: 64 bf16 payload + 8 pad = 72 elems = 144 bytes
#define LDT 144

// ---------------- routing ----------------
__global__ void route_kernel(const int* __restrict__ idx) {
    __shared__ int scnt[NE];
    int tid = threadIdx.x;
    if (tid < NE) scnt[tid] = 0;
    __syncthreads();
    for (int r = tid; r < RROWS; r += blockDim.x) {
        int e = idx[r];
        int p = atomicAdd(&scnt[e], 1);
        g_pos[r] = p;
        if (p < CAP) g_tok[e * CAP + p] = r >> 1;
    }
    __syncthreads();
    if (tid < NE) g_counts[tid] = scnt[tid];
}

// ---------------- weight split-conversion ----------------
__global__ void convert_split_kernel(const float4* __restrict__ src, int which, int nq) {
    __nv_bfloat162* dh;
    __nv_bfloat162* dl;
    if (which == 0)      { dh = (__nv_bfloat162*)g_gw_hi; dl = (__nv_bfloat162*)g_gw_lo; }
    else if (which == 1) { dh = (__nv_bfloat162*)g_uw_hi; dl = (__nv_bfloat162*)g_uw_lo; }
    else                 { dh = (__nv_bfloat162*)g_dw_hi; dl = (__nv_bfloat162*)g_dw_lo; }
    for (int i = blockIdx.x * blockDim.x + threadIdx.x; i < nq;
         i += gridDim.x * blockDim.x) {
        float4 v = src[i];
        __nv_bfloat162 h0, l0, h1, l1;
        split2(v.x, v.y, h0, l0);
        split2(v.z, v.w, h1, l1);
        dh[2 * i]     = h0; dh[2 * i + 1] = h1;
        dl[2 * i]     = l0; dl[2 * i + 1] = l1;
    }
}

// ---------------- dispatch: gather tokens into (E,C,K) bf16 hi/lo ----------------
__global__ void dispatch_kernel(const float* __restrict__ X) {
    int e = blockIdx.y, slot = blockIdx.x;
    if (slot >= g_counts[e]) return;
    int tok = g_tok[e * CAP + slot];
    const float4* src = (const float4*)(X + (size_t)tok * KDIM);
    __nv_bfloat162* dh = (__nv_bfloat162*)(g_a_hi + ((size_t)e * CAP + slot) * KDIM);
    __nv_bfloat162* dl = (__nv_bfloat162*)(g_a_lo + ((size_t)e * CAP + slot) * KDIM);
    for (int q = threadIdx.x; q < KDIM / 4; q += blockDim.x) {
        float4 v = src[q];
        __nv_bfloat162 h0, l0, h1, l1;
        split2(v.x, v.y, h0, l0);
        split2(v.z, v.w, h1, l1);
        dh[2 * q] = h0; dh[2 * q + 1] = h1;
        dl[2 * q] = l0; dl[2 * q + 1] = l1;
    }
}

// ---------------- tile loaders (cp.async, 16B chunks) ----------------
// tile: R rows x 64 bf16, dst rows padded to 144B
template <int R>
__device__ __forceinline__ void load_tile(uint32_t dst, const __nv_bfloat16* src,
                                          int ld_src, int tid) {
#pragma unroll
    for (int i = 0; i < (R * 8) / 256; i++) {
        int idx = i * 256 + tid;
        int row = idx >> 3;
        int c   = idx & 7;
        CPA(dst + row * LDT + c * 16,
            (const char*)src + (size_t)row * ld_src * 2 + c * 16);
    }
}

// ---------------- GEMM1: fused gate+up + SwiGLU ----------------
// stage layout (bytes): AH[0,18432) AL[18432,36864) BgH[36864,46080)
//                       BgL[46080,55296) BuH[55296,64512) BuL[64512,73728)
#define G1_STAGE 73728
#define G1_SMEM  (3 * G1_STAGE)
#define G1_NCH   (KDIM / 64)   // 32

__global__ __launch_bounds__(256, 1) void gemm1_kernel() {
    const int e   = blockIdx.z;
    const int cnt = g_counts[e];
    const int c0  = blockIdx.y * 128;
    if (c0 >= cnt) return;
    const int n0  = blockIdx.x * 64;
    const int tid = threadIdx.x;

    extern __shared__ char smem[];
    const uint32_t sb0 = smem_u32(smem);

    const int w    = tid >> 5;
    const int lane = tid & 31;
    const int wm   = w & 3;       // 32-row band
    const int wn   = w >> 2;      // 32-col half of the 64-wide N tile

    const __nv_bfloat16* aH  = g_a_hi + ((size_t)e * CAP + c0) * KDIM;
    const __nv_bfloat16* aL  = g_a_lo + ((size_t)e * CAP + c0) * KDIM;
    const __nv_bfloat16* bgH = g_gw_hi + ((size_t)e * NDIM + n0) * KDIM;
    const __nv_bfloat16* bgL = g_gw_lo + ((size_t)e * NDIM + n0) * KDIM;
    const __nv_bfloat16* buH = g_uw_hi + ((size_t)e * NDIM + n0) * KDIM;
    const __nv_bfloat16* buL = g_uw_lo + ((size_t)e * NDIM + n0) * KDIM;

    auto load_chunk = [&](int kc, int st) {
        uint32_t sb = sb0 + st * G1_STAGE;
        int ko = kc * 64;
        load_tile<128>(sb +     0, aH  + ko, KDIM, tid);
        load_tile<128>(sb + 18432, aL  + ko, KDIM, tid);
        load_tile<64>(sb + 36864, bgH + ko, KDIM, tid);
        load_tile<64>(sb + 46080, bgL + ko, KDIM, tid);
        load_tile<64>(sb + 55296, buH + ko, KDIM, tid);
        load_tile<64>(sb + 64512, buL + ko, KDIM, tid);
        CPC();
    };

    float cg[2][4][4], cu[2][4][4];
#pragma unroll
    for (int t = 0; t < 2; t++)
#pragma unroll
        for (int nt = 0; nt < 4; nt++)
#pragma unroll
            for (int j = 0; j < 4; j++) { cg[t][nt][j] = 0.f; cu[t][nt][j] = 0.f; }

    // ldmatrix base offsets (within a stage), depend only on lane
    const int lrow  = lane & 15;
    const int lkoff = (lane >> 4) * 16;   // 8 bf16 = 16 bytes

    load_chunk(0, 0);
    load_chunk(1, 1);

    for (int c = 0; c < G1_NCH; c++) {
        const int s = c % 3;
        if (c + 2 < G1_NCH) { CPW1(); } else { CPW0(); }
        __syncthreads();
        if (c + 2 < G1_NCH) load_chunk(c + 2, (c + 2) % 3);

        const uint32_t sb = sb0 + s * G1_STAGE;
#pragma unroll
        for (int kk = 0; kk < 4; kk++) {   // 4 x k16 within BK=64
            const uint32_t kb = kk * 32 + lkoff;   // byte offset along k
            uint32_t ah[2][4], al[2][4];
#pragma unroll
            for (int t = 0; t < 2; t++) {
                uint32_t r = (wm * 32 + t * 16 + lrow) * LDT + kb;
                ldsm_x4(ah[t], sb + r);
                ldsm_x4(al[t], sb + 18432 + r);
            }
            // gate
            {
                uint32_t bh[2][4], bl[2][4];
#pragma unroll
                for (int gix = 0; gix < 2; gix++) {
                    uint32_t r = (wn * 32 + gix * 16 + lrow) * LDT + kb;
                    ldsm_x4(bh[gix], sb + 36864 + r);
                    ldsm_x4(bl[gix], sb + 46080 + r);
                }
#pragma unroll
                for (int t = 0; t < 2; t++)
#pragma unroll
                    for (int nt = 0; nt < 4; nt++) {
                        int gix = nt >> 1, sub = nt & 1;
                        mma16816(cg[t][nt], ah[t], bh[gix][sub], bh[gix][sub + 2]);
                        mma16816(cg[t][nt], ah[t], bl[gix][sub], bl[gix][sub + 2]);
                        mma16816(cg[t][nt], al[t], bh[gix][sub], bh[gix][sub + 2]);
                    }
            }
            // up
            {
                uint32_t bh[2][4], bl[2][4];
#pragma unroll
                for (int gix = 0; gix < 2; gix++) {
                    uint32_t r = (wn * 32 + gix * 16 + lrow) * LDT + kb;
                    ldsm_x4(bh[gix], sb + 55296 + r);
                    ldsm_x4(bl[gix], sb + 64512 + r);
                }
#pragma unroll
                for (int t = 0; t < 2; t++)
#pragma unroll
                    for (int nt = 0; nt < 4; nt++) {
                        int gix = nt >> 1, sub = nt & 1;
                        mma16816(cu[t][nt], ah[t], bh[gix][sub], bh[gix][sub + 2]);
                        mma16816(cu[t][nt], ah[t], bl[gix][sub], bl[gix][sub + 2]);
                        mma16816(cu[t][nt], al[t], bh[gix][sub], bh[gix][sub + 2]);
                    }
            }
        }
    }

    // epilogue: SwiGLU, split to bf16 hi/lo, store to g_h
#pragma unroll
    for (int t = 0; t < 2; t++) {
#pragma unroll
        for (int jp = 0; jp < 2; jp++) {
            int crow = c0 + wm * 32 + t * 16 + (lane >> 2) + jp * 8;
            if (crow >= cnt) continue;
            size_t rowbase = ((size_t)e * CAP + crow) * NDIM + n0 + wn * 32;
#pragma unroll
            for (int nt = 0; nt < 4; nt++) {
                float g0 = fminf(cg[t][nt][jp * 2],     10.0f);
                float g1 = fminf(cg[t][nt][jp * 2 + 1], 10.0f);
                float u0 = fminf(fmaxf(cu[t][nt][jp * 2],     -10.0f), 10.0f);
                float u1 = fminf(fmaxf(cu[t][nt][jp * 2 + 1], -10.0f), 10.0f);
                float r0 = (g0 / (1.0f + __expf(-g0))) * u0;
                float r1 = (g1 / (1.0f + __expf(-g1))) * u1;
                __nv_bfloat162 hh, ll;
                split2(r0, r1, hh, ll);
                int ncol = nt * 8 + (lane & 3) * 2;
                *(__nv_bfloat162*)(g_h_hi + rowbase + ncol) = hh;
                *(__nv_bfloat162*)(g_h_lo + rowbase + ncol) = ll;
            }
        }
    }
}

// ---------------- GEMM2: down projection ----------------
// stage layout: AH[0,18432) AL[18432,36864) BH[36864,55296) BL[55296,73728)
#define G2_STAGE 73728
#define G2_SMEM  (3 * G2_STAGE)
#define G2_NCH   (NDIM / 64)   // 22

__global__ __launch_bounds__(256, 1) void gemm2_kernel() {
    const int e   = blockIdx.z;
    const int cnt = g_counts[e];
    const int c0  = blockIdx.y * 128;
    if (c0 >= cnt) return;
    const int k0  = blockIdx.x * 128;
    const int tid = threadIdx.x;

    extern __shared__ char smem[];
    const uint32_t sb0 = smem_u32(smem);

    const int w    = tid >> 5;
    const int lane = tid & 31;
    const int wm   = w & 3;      // 32-row band
    const int wn   = w >> 2;     // 64-col half

    const __nv_bfloat16* aH = g_h_hi + ((size_t)e * CAP + c0) * NDIM;
    const __nv_bfloat16* aL = g_h_lo + ((size_t)e * CAP + c0) * NDIM;
    const __nv_bfloat16* bH = g_dw_hi + ((size_t)e * KDIM + k0) * NDIM;
    const __nv_bfloat16* bL = g_dw_lo + ((size_t)e * KDIM + k0) * NDIM;

    auto load_chunk = [&](int kc, int st) {
        uint32_t sb = sb0 + st * G2_STAGE;
        int ko = kc * 64;
        load_tile<128>(sb +     0, aH + ko, NDIM, tid);
        load_tile<128>(sb + 18432, aL + ko, NDIM, tid);
        load_tile<128>(sb + 36864, bH + ko, NDIM, tid);
        load_tile<128>(sb + 55296, bL + ko, NDIM, tid);
        CPC();
    };

    float acc[2][8][4];
#pragma unroll
    for (int t = 0; t < 2; t++)
#pragma unroll
        for (int nt = 0; nt < 8; nt++)
#pragma unroll
            for (int j = 0; j < 4; j++) acc[t][nt][j] = 0.f;

    const int lrow  = lane & 15;
    const int lkoff = (lane >> 4) * 16;

    load_chunk(0, 0);
    load_chunk(1, 1);

    for (int c = 0; c < G2_NCH; c++) {
        const int s = c % 3;
        if (c + 2 < G2_NCH) { CPW1(); } else { CPW0(); }
        __syncthreads();
        if (c + 2 < G2_NCH) load_chunk(c + 2, (c + 2) % 3);

        const uint32_t sb = sb0 + s * G2_STAGE;
#pragma unroll
        for (int kk = 0; kk < 4; kk++) {
            const uint32_t kb = kk * 32 + lkoff;
            uint32_t ah[2][4], al[2][4];
#pragma unroll
            for (int t = 0; t < 2; t++) {
                uint32_t r = (wm * 32 + t * 16 + lrow) * LDT + kb;
                ldsm_x4(ah[t], sb + r);
                ldsm_x4(al[t], sb + 18432 + r);
            }
            uint32_t bh[4][4], bl[4][4];
#pragma unroll
            for (int gix = 0; gix < 4; gix++) {
                uint32_t r = (wn * 64 + gix * 16 + lrow) * LDT + kb;
                ldsm_x4(bh[gix], sb + 36864 + r);
                ldsm_x4(bl[gix], sb + 55296 + r);
            }
#pragma unroll
            for (int t = 0; t < 2; t++)
#pragma unroll
                for (int nt = 0; nt < 8; nt++) {
                    int gix = nt >> 1, sub = nt & 1;
                    mma16816(acc[t][nt], ah[t], bh[gix][sub], bh[gix][sub + 2]);
                    mma16816(acc[t][nt], ah[t], bl[gix][sub], bl[gix][sub + 2]);
                    mma16816(acc[t][nt], al[t], bh[gix][sub], bh[gix][sub + 2]);
                }
        }
    }

    // epilogue: fp32 store to g_d
#pragma unroll
    for (int t = 0; t < 2; t++) {
#pragma unroll
        for (int jp = 0; jp < 2; jp++) {
            int crow = c0 + wm * 32 + t * 16 + (lane >> 2) + jp * 8;
            if (crow >= cnt) continue;
            float* dst = g_d + ((size_t)e * CAP + crow) * KDIM + k0 + wn * 64;
#pragma unroll
            for (int nt = 0; nt < 8; nt++) {
                float2 v;
                v.x = acc[t][nt][jp * 2];
                v.y = acc[t][nt][jp * 2 + 1];
                *(float2*)(dst + nt * 8 + (lane & 3) * 2) = v;
            }
        }
    }
}

// ---------------- combine ----------------
__global__ void combine_kernel(const int* __restrict__ idx,
                               const float* __restrict__ gate,
                               float* __restrict__ out)
{
    const int t = blockIdx.x;
    const int e0 = idx[2 * t], e1 = idx[2 * t + 1];
    const float w0 = gate[2 * t], w1 = gate[2 * t + 1];
    const int p0 = g_pos[2 * t], p1 = g_pos[2 * t + 1];
    const float* d0 = g_d + ((size_t)e0 * CAP + p0) * KDIM;
    const float* d1 = g_d + ((size_t)e1 * CAP + p1) * KDIM;
    float* o = out + (size_t)t * KDIM;

    for (int k = threadIdx.x * 4; k < KDIM; k += blockDim.x * 4) {
        float4 a = *(const float4*)(d0 + k);
        float4 b = *(const float4*)(d1 + k);
        float4 r;
        r.x = w0 * a.x + w1 * b.x;
        r.y = w0 * a.y + w1 * b.y;
        r.z = w0 * a.z + w1 * b.z;
        r.w = w0 * a.w + w1 * b.w;
        *(float4*)(o + k) = r;
    }
}

// ---------------- launch ----------------
extern "C" void kernel_launch(void* const* d_in, const int* in_sizes, int n_in,
                              void* d_out, int out_size)
{
    const float* X    = (const float*)d_in[0];  // flat_h      (M,K)
    const int*   idx  = (const int*)  d_in[1];  // flat_idx    (M,TOPK)
    const float* gate = (const float*)d_in[2];  // flat_gate   (M,TOPK)
    const float* GW   = (const float*)d_in[3];  // gate_weight (E,N,K)
    const float* UW   = (const float*)d_in[4];  // up_weight   (E,N,K)
    const float* DW   = (const float*)d_in[5];  // down_weight (E,K,N)
    float* out = (float*)d_out;

    cudaFuncSetAttribute(gemm1_kernel, cudaFuncAttributeMaxDynamicSharedMemorySize, G1_SMEM);
    cudaFuncSetAttribute(gemm2_kernel, cudaFuncAttributeMaxDynamicSharedMemorySize, G2_SMEM);

    const int nq = (NE * NDIM * KDIM) / 4;

    route_kernel<<<1, 256>>>(idx);
    convert_split_kernel<<<2048, 256>>>((const float4*)GW, 0, nq);
    convert_split_kernel<<<2048, 256>>>((const float4*)UW, 1, nq);
    convert_split_kernel<<<2048, 256>>>((const float4*)DW, 2, nq);
    dispatch_kernel<<<dim3(CAP, NE), 256>>>(X);

    dim3 g1(NDIM / 64, CAP / 128, NE);    // (22, 8, 8)
    gemm1_kernel<<<g1, 256, G1_SMEM>>>();

    dim3 g2(KDIM / 128, CAP / 128, NE);   // (16, 8, 8)
    gemm2_kernel<<<g2, 256, G2_SMEM>>>();

    combine_kernel<<<MTOK, 256>>>(idx, gate, out);
}

// round 4
// speedup vs baseline: 2.0115x; 1.0204x over previous
#include <cuda_runtime.h>
#include <cuda_bf16.h>
#include <math.h>
#include <stdint.h>

#define NE      8
#define TOPK    2
#define MTOK    2048
#define KDIM    2048
#define NDIM    1408
#define CAP     1024
#define RROWS   (MTOK * TOPK)

// ---------------- scratch (device globals; no allocations) ----------------
__device__ int   g_counts[NE];
__device__ int   g_tok[NE * CAP];
__device__ int   g_pos[RROWS];
__device__ __nv_bfloat16 g_a_hi[(size_t)NE * CAP * KDIM];
__device__ __nv_bfloat16 g_a_lo[(size_t)NE * CAP * KDIM];
__device__ __nv_bfloat16 g_gw_hi[(size_t)NE * NDIM * KDIM];
__device__ __nv_bfloat16 g_gw_lo[(size_t)NE * NDIM * KDIM];
__device__ __nv_bfloat16 g_uw_hi[(size_t)NE * NDIM * KDIM];
__device__ __nv_bfloat16 g_uw_lo[(size_t)NE * NDIM * KDIM];
__device__ __nv_bfloat16 g_dw_hi[(size_t)NE * KDIM * NDIM];
__device__ __nv_bfloat16 g_dw_lo[(size_t)NE * KDIM * NDIM];
__device__ __nv_bfloat16 g_h_hi[(size_t)NE * CAP * NDIM];
__device__ __nv_bfloat16 g_h_lo[(size_t)NE * CAP * NDIM];
__device__ float g_d[(size_t)NE * CAP * KDIM];

// ---------------- helpers ----------------
__device__ __forceinline__ uint32_t smem_u32(const void* p) {
    return (uint32_t)__cvta_generic_to_shared(p);
}

#define CPA(dst, src) \
    asm volatile("cp.async.cg.shared.global [%0], [%1], 16;" :: "r"(dst), "l"(src) : "memory")
#define CPC()  asm volatile("cp.async.commit_group;" ::: "memory")
#define CPW1() asm volatile("cp.async.wait_group 1;" ::: "memory")
#define CPW0() asm volatile("cp.async.wait_group 0;" ::: "memory")

__device__ __forceinline__ void ldsm_x4(uint32_t* r, uint32_t a) {
    asm volatile("ldmatrix.sync.aligned.m8n8.x4.shared.b16 {%0,%1,%2,%3}, [%4];"
        : "=r"(r[0]), "=r"(r[1]), "=r"(r[2]), "=r"(r[3]) : "r"(a));
}

__device__ __forceinline__ void mma16816(float* c, const uint32_t* a,
                                         uint32_t b0, uint32_t b1) {
    asm volatile(
        "mma.sync.aligned.m16n8k16.row.col.f32.bf16.bf16.f32 "
        "{%0,%1,%2,%3}, {%4,%5,%6,%7}, {%8,%9}, {%0,%1,%2,%3};"
        : "+f"(c[0]), "+f"(c[1]), "+f"(c[2]), "+f"(c[3])
        : "r"(a[0]), "r"(a[1]), "r"(a[2]), "r"(a[3]), "r"(b0), "r"(b1));
}

__device__ __forceinline__ void split2(float a, float b,
                                       __nv_bfloat162& hi, __nv_bfloat162& lo) {
    __nv_bfloat16 ha = __float2bfloat16(a);
    __nv_bfloat16 hb = __float2bfloat16(b);
    hi.x = ha; hi.y = hb;
    lo.x = __float2bfloat16(a - __bfloat162float(ha));
    lo.y = __float2bfloat16(b - __bfloat162float(hb));
}

// padded tile row: 64 bf16 payload + 8 pad = 72 elems = 144 bytes
#define LDT   144
#define TILE  18432      // 128 rows * 144 B

// ---------------- routing ----------------
__global__ void route_kernel(const int* __restrict__ idx) {
    __shared__ int scnt[NE];
    int tid = threadIdx.x;
    if (tid < NE) scnt[tid] = 0;
    __syncthreads();
    for (int r = tid; r < RROWS; r += blockDim.x) {
        int e = idx[r];
        int p = atomicAdd(&scnt[e], 1);
        g_pos[r] = p;
        if (p < CAP) g_tok[e * CAP + p] = r >> 1;
    }
    __syncthreads();
    if (tid < NE) g_counts[tid] = scnt[tid];
}

// ---------------- fused weight split-conversion (all 3 tensors) ----------------
#define WQ ((NE * NDIM * KDIM) / 4)   // float4 count per weight tensor
__global__ void convert_all_kernel(const float4* __restrict__ GW,
                                   const float4* __restrict__ UW,
                                   const float4* __restrict__ DW) {
    for (int i = blockIdx.x * blockDim.x + threadIdx.x; i < 3 * WQ;
         i += gridDim.x * blockDim.x) {
        const float4* s;
        __nv_bfloat162* dh;
        __nv_bfloat162* dl;
        int j;
        if (i < WQ) {
            j = i; s = GW; dh = (__nv_bfloat162*)g_gw_hi; dl = (__nv_bfloat162*)g_gw_lo;
        } else if (i < 2 * WQ) {
            j = i - WQ; s = UW; dh = (__nv_bfloat162*)g_uw_hi; dl = (__nv_bfloat162*)g_uw_lo;
        } else {
            j = i - 2 * WQ; s = DW; dh = (__nv_bfloat162*)g_dw_hi; dl = (__nv_bfloat162*)g_dw_lo;
        }
        float4 v = s[j];
        __nv_bfloat162 h0, l0, h1, l1;
        split2(v.x, v.y, h0, l0);
        split2(v.z, v.w, h1, l1);
        dh[2 * j]     = h0; dh[2 * j + 1] = h1;
        dl[2 * j]     = l0; dl[2 * j + 1] = l1;
    }
}

// ---------------- dispatch: gather tokens into (E,C,K) bf16 hi/lo ----------------
__global__ void dispatch_kernel(const float* __restrict__ X) {
    int e = blockIdx.y, slot = blockIdx.x;
    if (slot >= g_counts[e]) return;
    int tok = g_tok[e * CAP + slot];
    const float4* src = (const float4*)(X + (size_t)tok * KDIM);
    __nv_bfloat162* dh = (__nv_bfloat162*)(g_a_hi + ((size_t)e * CAP + slot) * KDIM);
    __nv_bfloat162* dl = (__nv_bfloat162*)(g_a_lo + ((size_t)e * CAP + slot) * KDIM);
    for (int q = threadIdx.x; q < KDIM / 4; q += blockDim.x) {
        float4 v = src[q];
        __nv_bfloat162 h0, l0, h1, l1;
        split2(v.x, v.y, h0, l0);
        split2(v.z, v.w, h1, l1);
        dh[2 * q] = h0; dh[2 * q + 1] = h1;
        dl[2 * q] = l0; dl[2 * q + 1] = l1;
    }
}

// ---------------- tile loader: 128 rows x 64 bf16, rows padded to 144B ----------------
__device__ __forceinline__ void load_tile(uint32_t dst, const __nv_bfloat16* src,
                                          int ld_src, int tid) {
#pragma unroll
    for (int i = 0; i < 4; i++) {
        int idx = i * 256 + tid;
        int row = idx >> 3;
        int c   = idx & 7;
        CPA(dst + row * LDT + c * 16,
            (const char*)src + (size_t)row * ld_src * 2 + c * 16);
    }
}

// ---------------- GEMM1: fused gate+up + SwiGLU ----------------
// stage: AH AL BgH BgL BuH BuL, each TILE bytes -> 110592 B/stage, 2 stages
#define G1_STAGE (6 * TILE)
#define G1_SMEM  (2 * G1_STAGE)
#define G1_NCH   (KDIM / 64)   // 32

__global__ __launch_bounds__(256, 1) void gemm1_kernel() {
    const int e   = blockIdx.z;
    const int cnt = g_counts[e];
    const int c0  = blockIdx.y * 128;
    if (c0 >= cnt) return;
    const int n0  = blockIdx.x * 128;
    const int tid = threadIdx.x;

    extern __shared__ char smem[];
    const uint32_t sb0 = smem_u32(smem);

    const int w    = tid >> 5;
    const int lane = tid & 31;
    const int wm   = w & 1;       // 64-row band
    const int wn   = w >> 1;      // 32-col group (0..3)

    const __nv_bfloat16* aH  = g_a_hi + ((size_t)e * CAP + c0) * KDIM;
    const __nv_bfloat16* aL  = g_a_lo + ((size_t)e * CAP + c0) * KDIM;
    const __nv_bfloat16* bgH = g_gw_hi + ((size_t)e * NDIM + n0) * KDIM;
    const __nv_bfloat16* bgL = g_gw_lo + ((size_t)e * NDIM + n0) * KDIM;
    const __nv_bfloat16* buH = g_uw_hi + ((size_t)e * NDIM + n0) * KDIM;
    const __nv_bfloat16* buL = g_uw_lo + ((size_t)e * NDIM + n0) * KDIM;

    auto load_chunk = [&](int kc, int st) {
        uint32_t sb = sb0 + st * G1_STAGE;
        int ko = kc * 64;
        load_tile(sb + 0 * TILE, aH  + ko, KDIM, tid);
        load_tile(sb + 1 * TILE, aL  + ko, KDIM, tid);
        load_tile(sb + 2 * TILE, bgH + ko, KDIM, tid);
        load_tile(sb + 3 * TILE, bgL + ko, KDIM, tid);
        load_tile(sb + 4 * TILE, buH + ko, KDIM, tid);
        load_tile(sb + 5 * TILE, buL + ko, KDIM, tid);
        CPC();
    };

    float cg[4][4][4], cu[4][4][4];
#pragma unroll
    for (int t = 0; t < 4; t++)
#pragma unroll
        for (int nt = 0; nt < 4; nt++)
#pragma unroll
            for (int j = 0; j < 4; j++) { cg[t][nt][j] = 0.f; cu[t][nt][j] = 0.f; }

    const int lrow  = lane & 15;
    const int lkoff = (lane >> 4) * 16;

    load_chunk(0, 0);
    load_chunk(1, 1);

    for (int c = 0; c < G1_NCH; c++) {
        const int s = c & 1;
        if (c + 1 < G1_NCH) { CPW1(); } else { CPW0(); }
        __syncthreads();

        const uint32_t sb = sb0 + s * G1_STAGE;
#pragma unroll
        for (int kk = 0; kk < 4; kk++) {
            const uint32_t kb = kk * 32 + lkoff;
            uint32_t ah[4][4], al[4][4];
#pragma unroll
            for (int t = 0; t < 4; t++) {
                uint32_t r = (wm * 64 + t * 16 + lrow) * LDT + kb;
                ldsm_x4(ah[t], sb + r);
                ldsm_x4(al[t], sb + TILE + r);
            }
            // gate
            {
                uint32_t bh[2][4], bl[2][4];
#pragma unroll
                for (int gix = 0; gix < 2; gix++) {
                    uint32_t r = (wn * 32 + gix * 16 + lrow) * LDT + kb;
                    ldsm_x4(bh[gix], sb + 2 * TILE + r);
                    ldsm_x4(bl[gix], sb + 3 * TILE + r);
                }
#pragma unroll
                for (int t = 0; t < 4; t++)
#pragma unroll
                    for (int nt = 0; nt < 4; nt++) {
                        int gix = nt >> 1, sub = nt & 1;
                        mma16816(cg[t][nt], ah[t], bh[gix][sub], bh[gix][sub + 2]);
                        mma16816(cg[t][nt], ah[t], bl[gix][sub], bl[gix][sub + 2]);
                        mma16816(cg[t][nt], al[t], bh[gix][sub], bh[gix][sub + 2]);
                    }
            }
            // up
            {
                uint32_t bh[2][4], bl[2][4];
#pragma unroll
                for (int gix = 0; gix < 2; gix++) {
                    uint32_t r = (wn * 32 + gix * 16 + lrow) * LDT + kb;
                    ldsm_x4(bh[gix], sb + 4 * TILE + r);
                    ldsm_x4(bl[gix], sb + 5 * TILE + r);
                }
#pragma unroll
                for (int t = 0; t < 4; t++)
#pragma unroll
                    for (int nt = 0; nt < 4; nt++) {
                        int gix = nt >> 1, sub = nt & 1;
                        mma16816(cu[t][nt], ah[t], bh[gix][sub], bh[gix][sub + 2]);
                        mma16816(cu[t][nt], ah[t], bl[gix][sub], bl[gix][sub + 2]);
                        mma16816(cu[t][nt], al[t], bh[gix][sub], bh[gix][sub + 2]);
                    }
            }
        }
        __syncthreads();
        if (c + 2 < G1_NCH) load_chunk(c + 2, s);
    }

    // epilogue: SwiGLU, split to bf16 hi/lo, store to g_h
#pragma unroll
    for (int t = 0; t < 4; t++) {
#pragma unroll
        for (int jp = 0; jp < 2; jp++) {
            int crow = c0 + wm * 64 + t * 16 + (lane >> 2) + jp * 8;
            if (crow >= cnt) continue;
            size_t rowbase = ((size_t)e * CAP + crow) * NDIM + n0 + wn * 32;
#pragma unroll
            for (int nt = 0; nt < 4; nt++) {
                float g0 = fminf(cg[t][nt][jp * 2],     10.0f);
                float g1 = fminf(cg[t][nt][jp * 2 + 1], 10.0f);
                float u0 = fminf(fmaxf(cu[t][nt][jp * 2],     -10.0f), 10.0f);
                float u1 = fminf(fmaxf(cu[t][nt][jp * 2 + 1], -10.0f), 10.0f);
                float r0 = (g0 / (1.0f + __expf(-g0))) * u0;
                float r1 = (g1 / (1.0f + __expf(-g1))) * u1;
                __nv_bfloat162 hh, ll;
                split2(r0, r1, hh, ll);
                int ncol = nt * 8 + (lane & 3) * 2;
                *(__nv_bfloat162*)(g_h_hi + rowbase + ncol) = hh;
                *(__nv_bfloat162*)(g_h_lo + rowbase + ncol) = ll;
            }
        }
    }
}

// ---------------- GEMM2: down projection ----------------
// stage: AH AL BH BL, each TILE -> 73728 B/stage, 3 stages
#define G2_STAGE (4 * TILE)
#define G2_SMEM  (3 * G2_STAGE)
#define G2_NCH   (NDIM / 64)   // 22

__global__ __launch_bounds__(256, 1) void gemm2_kernel() {
    const int e   = blockIdx.z;
    const int cnt = g_counts[e];
    const int c0  = blockIdx.y * 128;
    if (c0 >= cnt) return;
    const int k0  = blockIdx.x * 128;
    const int tid = threadIdx.x;

    extern __shared__ char smem[];
    const uint32_t sb0 = smem_u32(smem);

    const int w    = tid >> 5;
    const int lane = tid & 31;
    const int wm   = w & 1;      // 64-row band
    const int wn   = w >> 1;     // 32-col group

    const __nv_bfloat16* aH = g_h_hi + ((size_t)e * CAP + c0) * NDIM;
    const __nv_bfloat16* aL = g_h_lo + ((size_t)e * CAP + c0) * NDIM;
    const __nv_bfloat16* bH = g_dw_hi + ((size_t)e * KDIM + k0) * NDIM;
    const __nv_bfloat16* bL = g_dw_lo + ((size_t)e * KDIM + k0) * NDIM;

    auto load_chunk = [&](int kc, int st) {
        uint32_t sb = sb0 + st * G2_STAGE;
        int ko = kc * 64;
        load_tile(sb + 0 * TILE, aH + ko, NDIM, tid);
        load_tile(sb + 1 * TILE, aL + ko, NDIM, tid);
        load_tile(sb + 2 * TILE, bH + ko, NDIM, tid);
        load_tile(sb + 3 * TILE, bL + ko, NDIM, tid);
        CPC();
    };

    float acc[4][4][4];
#pragma unroll
    for (int t = 0; t < 4; t++)
#pragma unroll
        for (int nt = 0; nt < 4; nt++)
#pragma unroll
            for (int j = 0; j < 4; j++) acc[t][nt][j] = 0.f;

    const int lrow  = lane & 15;
    const int lkoff = (lane >> 4) * 16;

    load_chunk(0, 0);
    load_chunk(1, 1);

    for (int c = 0; c < G2_NCH; c++) {
        const int s = c % 3;
        if (c + 2 < G2_NCH) { CPW1(); } else { CPW0(); }
        __syncthreads();
        if (c + 2 < G2_NCH) load_chunk(c + 2, (c + 2) % 3);

        const uint32_t sb = sb0 + s * G2_STAGE;
#pragma unroll
        for (int kk = 0; kk < 4; kk++) {
            const uint32_t kb = kk * 32 + lkoff;
            uint32_t ah[4][4], al[4][4];
#pragma unroll
            for (int t = 0; t < 4; t++) {
                uint32_t r = (wm * 64 + t * 16 + lrow) * LDT + kb;
                ldsm_x4(ah[t], sb + r);
                ldsm_x4(al[t], sb + TILE + r);
            }
            uint32_t bh[2][4], bl[2][4];
#pragma unroll
            for (int gix = 0; gix < 2; gix++) {
                uint32_t r = (wn * 32 + gix * 16 + lrow) * LDT + kb;
                ldsm_x4(bh[gix], sb + 2 * TILE + r);
                ldsm_x4(bl[gix], sb + 3 * TILE + r);
            }
#pragma unroll
            for (int t = 0; t < 4; t++)
#pragma unroll
                for (int nt = 0; nt < 4; nt++) {
                    int gix = nt >> 1, sub = nt & 1;
                    mma16816(acc[t][nt], ah[t], bh[gix][sub], bh[gix][sub + 2]);
                    mma16816(acc[t][nt], ah[t], bl[gix][sub], bl[gix][sub + 2]);
                    mma16816(acc[t][nt], al[t], bh[gix][sub], bh[gix][sub + 2]);
                }
        }
    }

    // epilogue: fp32 store to g_d
#pragma unroll
    for (int t = 0; t < 4; t++) {
#pragma unroll
        for (int jp = 0; jp < 2; jp++) {
            int crow = c0 + wm * 64 + t * 16 + (lane >> 2) + jp * 8;
            if (crow >= cnt) continue;
            float* dst = g_d + ((size_t)e * CAP + crow) * KDIM + k0 + wn * 32;
#pragma unroll
            for (int nt = 0; nt < 4; nt++) {
                float2 v;
                v.x = acc[t][nt][jp * 2];
                v.y = acc[t][nt][jp * 2 + 1];
                *(float2*)(dst + nt * 8 + (lane & 3) * 2) = v;
            }
        }
    }
}

// ---------------- combine ----------------
__global__ void combine_kernel(const int* __restrict__ idx,
                               const float* __restrict__ gate,
                               float* __restrict__ out)
{
    const int t = blockIdx.x;
    const int e0 = idx[2 * t], e1 = idx[2 * t + 1];
    const float w0 = gate[2 * t], w1 = gate[2 * t + 1];
    const int p0 = g_pos[2 * t], p1 = g_pos[2 * t + 1];
    const float* d0 = g_d + ((size_t)e0 * CAP + p0) * KDIM;
    const float* d1 = g_d + ((size_t)e1 * CAP + p1) * KDIM;
    float* o = out + (size_t)t * KDIM;

    for (int k = threadIdx.x * 4; k < KDIM; k += blockDim.x * 4) {
        float4 a = *(const float4*)(d0 + k);
        float4 b = *(const float4*)(d1 + k);
        float4 r;
        r.x = w0 * a.x + w1 * b.x;
        r.y = w0 * a.y + w1 * b.y;
        r.z = w0 * a.z + w1 * b.z;
        r.w = w0 * a.w + w1 * b.w;
        *(float4*)(o + k) = r;
    }
}

// ---------------- launch ----------------
extern "C" void kernel_launch(void* const* d_in, const int* in_sizes, int n_in,
                              void* d_out, int out_size)
{
    const float* X    = (const float*)d_in[0];  // flat_h      (M,K)
    const int*   idx  = (const int*)  d_in[1];  // flat_idx    (M,TOPK)
    const float* gate = (const float*)d_in[2];  // flat_gate   (M,TOPK)
    const float* GW   = (const float*)d_in[3];  // gate_weight (E,N,K)
    const float* UW   = (const float*)d_in[4];  // up_weight   (E,N,K)
    const float* DW   = (const float*)d_in[5];  // down_weight (E,K,N)
    float* out = (float*)d_out;

    cudaFuncSetAttribute(gemm1_kernel, cudaFuncAttributeMaxDynamicSharedMemorySize, G1_SMEM);
    cudaFuncSetAttribute(gemm2_kernel, cudaFuncAttributeMaxDynamicSharedMemorySize, G2_SMEM);

    route_kernel<<<1, 256>>>(idx);
    convert_all_kernel<<<4096, 256>>>((const float4*)GW, (const float4*)UW,
                                      (const float4*)DW);
    dispatch_kernel<<<dim3(CAP, NE), 256>>>(X);

    dim3 g1(NDIM / 128, CAP / 128, NE);   // (11, 8, 8)
    gemm1_kernel<<<g1, 256, G1_SMEM>>>();

    dim3 g2(KDIM / 128, CAP / 128, NE);   // (16, 8, 8)
    gemm2_kernel<<<g2, 256, G2_SMEM>>>();

    combine_kernel<<<MTOK, 256>>>(idx, gate, out);
}

// round 6
// speedup vs baseline: 2.0999x; 1.0440x over previous
#include <cuda_runtime.h>
#include <cuda_bf16.h>
#include <math.h>
#include <stdint.h>

#define NE      8
#define TOPK    2
#define MTOK    2048
#define KDIM    2048
#define NDIM    1408
#define CAP     1024
#define RROWS   (MTOK * TOPK)

// ---------------- scratch (device globals; no allocations) ----------------
__device__ int   g_counts[NE];
__device__ int   g_tok[NE * CAP];
__device__ int   g_pos[RROWS];
__device__ __nv_bfloat16 g_a_hi[(size_t)NE * CAP * KDIM];
__device__ __nv_bfloat16 g_a_lo[(size_t)NE * CAP * KDIM];
__device__ __nv_bfloat16 g_gw_hi[(size_t)NE * NDIM * KDIM];
__device__ __nv_bfloat16 g_gw_lo[(size_t)NE * NDIM * KDIM];
__device__ __nv_bfloat16 g_uw_hi[(size_t)NE * NDIM * KDIM];
__device__ __nv_bfloat16 g_uw_lo[(size_t)NE * NDIM * KDIM];
__device__ __nv_bfloat16 g_dw_hi[(size_t)NE * KDIM * NDIM];
__device__ __nv_bfloat16 g_dw_lo[(size_t)NE * KDIM * NDIM];
__device__ __nv_bfloat16 g_h_hi[(size_t)NE * CAP * NDIM];
__device__ __nv_bfloat16 g_h_lo[(size_t)NE * CAP * NDIM];
__device__ float g_d[(size_t)NE * CAP * KDIM];

// ---------------- helpers ----------------
__device__ __forceinline__ uint32_t smem_u32(const void* p) {
    return (uint32_t)__cvta_generic_to_shared(p);
}

#define CPA(dst, src) \
    asm volatile("cp.async.cg.shared.global [%0], [%1], 16;" :: "r"(dst), "l"(src) : "memory")
#define CPC()  asm volatile("cp.async.commit_group;" ::: "memory")
#define CPW1() asm volatile("cp.async.wait_group 1;" ::: "memory")
#define CPW0() asm volatile("cp.async.wait_group 0;" ::: "memory")

__device__ __forceinline__ void ldsm_x4(uint32_t* r, uint32_t a) {
    asm volatile("ldmatrix.sync.aligned.m8n8.x4.shared.b16 {%0,%1,%2,%3}, [%4];"
        : "=r"(r[0]), "=r"(r[1]), "=r"(r[2]), "=r"(r[3]) : "r"(a));
}

__device__ __forceinline__ void mma16816(float* c, const uint32_t* a,
                                         uint32_t b0, uint32_t b1) {
    asm volatile(
        "mma.sync.aligned.m16n8k16.row.col.f32.bf16.bf16.f32 "
        "{%0,%1,%2,%3}, {%4,%5,%6,%7}, {%8,%9}, {%0,%1,%2,%3};"
        : "+f"(c[0]), "+f"(c[1]), "+f"(c[2]), "+f"(c[3])
        : "r"(a[0]), "r"(a[1]), "r"(a[2]), "r"(a[3]), "r"(b0), "r"(b1));
}

__device__ __forceinline__ void split2(float a, float b,
                                       __nv_bfloat162& hi, __nv_bfloat162& lo) {
    __nv_bfloat16 ha = __float2bfloat16(a);
    __nv_bfloat16 hb = __float2bfloat16(b);
    hi.x = ha; hi.y = hb;
    lo.x = __float2bfloat16(a - __bfloat162float(ha));
    lo.y = __float2bfloat16(b - __bfloat162float(hb));
}

// padded tile row: 64 bf16 payload + 8 pad = 72 elems = 144 bytes
#define LDT   144
#define TILE  18432      // 128 rows * 144 B

// ---------------- routing ----------------
__global__ void route_kernel(const int* __restrict__ idx) {
    __shared__ int scnt[NE];
    int tid = threadIdx.x;
    if (tid < NE) scnt[tid] = 0;
    __syncthreads();
    for (int r = tid; r < RROWS; r += blockDim.x) {
        int e = idx[r];
        int p = atomicAdd(&scnt[e], 1);
        g_pos[r] = p;
        if (p < CAP) g_tok[e * CAP + p] = r >> 1;
    }
    __syncthreads();
    if (tid < NE) g_counts[tid] = scnt[tid];
}

// ---------------- fused weight split-conversion (all 3 tensors) ----------------
#define WQ ((NE * NDIM * KDIM) / 4)   // float4 count per weight tensor
__global__ void convert_all_kernel(const float4* __restrict__ GW,
                                   const float4* __restrict__ UW,
                                   const float4* __restrict__ DW) {
    for (int i = blockIdx.x * blockDim.x + threadIdx.x; i < 3 * WQ;
         i += gridDim.x * blockDim.x) {
        const float4* s;
        __nv_bfloat162* dh;
        __nv_bfloat162* dl;
        int j;
        if (i < WQ) {
            j = i; s = GW; dh = (__nv_bfloat162*)g_gw_hi; dl = (__nv_bfloat162*)g_gw_lo;
        } else if (i < 2 * WQ) {
            j = i - WQ; s = UW; dh = (__nv_bfloat162*)g_uw_hi; dl = (__nv_bfloat162*)g_uw_lo;
        } else {
            j = i - 2 * WQ; s = DW; dh = (__nv_bfloat162*)g_dw_hi; dl = (__nv_bfloat162*)g_dw_lo;
        }
        float4 v = s[j];
        __nv_bfloat162 h0, l0, h1, l1;
        split2(v.x, v.y, h0, l0);
        split2(v.z, v.w, h1, l1);
        dh[2 * j]     = h0; dh[2 * j + 1] = h1;
        dl[2 * j]     = l0; dl[2 * j + 1] = l1;
    }
}

// ---------------- dispatch: gather tokens into (E,C,K) bf16 hi/lo ----------------
__global__ void dispatch_kernel(const float* __restrict__ X) {
    int e = blockIdx.y, slot = blockIdx.x;
    if (slot >= g_counts[e]) return;
    int tok = g_tok[e * CAP + slot];
    const float4* src = (const float4*)(X + (size_t)tok * KDIM);
    __nv_bfloat162* dh = (__nv_bfloat162*)(g_a_hi + ((size_t)e * CAP + slot) * KDIM);
    __nv_bfloat162* dl = (__nv_bfloat162*)(g_a_lo + ((size_t)e * CAP + slot) * KDIM);
    for (int q = threadIdx.x; q < KDIM / 4; q += blockDim.x) {
        float4 v = src[q];
        __nv_bfloat162 h0, l0, h1, l1;
        split2(v.x, v.y, h0, l0);
        split2(v.z, v.w, h1, l1);
        dh[2 * q] = h0; dh[2 * q + 1] = h1;
        dl[2 * q] = l0; dl[2 * q + 1] = l1;
    }
}

// ---------------- tile loader: 128 rows x 64 bf16, rows padded to 144B ----------------
// 512 threads: 2 iterations cover 1024 16B transfers
__device__ __forceinline__ void load_tile(uint32_t dst, const __nv_bfloat16* src,
                                          int ld_src, int tid) {
#pragma unroll
    for (int i = 0; i < 2; i++) {
        int idx = i * 512 + tid;
        int row = idx >> 3;
        int c   = idx & 7;
        CPA(dst + row * LDT + c * 16,
            (const char*)src + (size_t)row * ld_src * 2 + c * 16);
    }
}

// ---------------- GEMM1: fused gate+up + SwiGLU ----------------
// stage: AH AL BgH BgL BuH BuL, each TILE bytes -> 110592 B/stage, 2 stages
#define G1_STAGE (6 * TILE)
#define G1_SMEM  (2 * G1_STAGE)
#define G1_NCH   (KDIM / 64)   // 32

__global__ __launch_bounds__(512, 1) void gemm1_kernel() {
    const int e   = blockIdx.z;
    const int cnt = g_counts[e];
    const int c0  = blockIdx.y * 128;
    if (c0 >= cnt) return;
    const int n0  = blockIdx.x * 128;
    const int tid = threadIdx.x;

    extern __shared__ char smem[];
    const uint32_t sb0 = smem_u32(smem);

    const int w    = tid >> 5;
    const int lane = tid & 31;
    const int wm   = w & 3;       // 32-row band (0..3)
    const int wn   = w >> 2;      // 32-col group (0..3)

    const __nv_bfloat16* aH  = g_a_hi + ((size_t)e * CAP + c0) * KDIM;
    const __nv_bfloat16* aL  = g_a_lo + ((size_t)e * CAP + c0) * KDIM;
    const __nv_bfloat16* bgH = g_gw_hi + ((size_t)e * NDIM + n0) * KDIM;
    const __nv_bfloat16* bgL = g_gw_lo + ((size_t)e * NDIM + n0) * KDIM;
    const __nv_bfloat16* buH = g_uw_hi + ((size_t)e * NDIM + n0) * KDIM;
    const __nv_bfloat16* buL = g_uw_lo + ((size_t)e * NDIM + n0) * KDIM;

    auto load_chunk = [&](int kc, int st) {
        uint32_t sb = sb0 + st * G1_STAGE;
        int ko = kc * 64;
        load_tile(sb + 0 * TILE, aH  + ko, KDIM, tid);
        load_tile(sb + 1 * TILE, aL  + ko, KDIM, tid);
        load_tile(sb + 2 * TILE, bgH + ko, KDIM, tid);
        load_tile(sb + 3 * TILE, bgL + ko, KDIM, tid);
        load_tile(sb + 4 * TILE, buH + ko, KDIM, tid);
        load_tile(sb + 5 * TILE, buL + ko, KDIM, tid);
        CPC();
    };

    float cg[2][4][4], cu[2][4][4];
#pragma unroll
    for (int t = 0; t < 2; t++)
#pragma unroll
        for (int nt = 0; nt < 4; nt++)
#pragma unroll
            for (int j = 0; j < 4; j++) { cg[t][nt][j] = 0.f; cu[t][nt][j] = 0.f; }

    const int lrow  = lane & 15;
    const int lkoff = (lane >> 4) * 16;

    load_chunk(0, 0);
    load_chunk(1, 1);

    for (int c = 0; c < G1_NCH; c++) {
        const int s = c & 1;
        if (c + 1 < G1_NCH) { CPW1(); } else { CPW0(); }
        __syncthreads();

        const uint32_t sb = sb0 + s * G1_STAGE;
#pragma unroll
        for (int kk = 0; kk < 4; kk++) {
            const uint32_t kb = kk * 32 + lkoff;
            uint32_t ah[2][4], al[2][4];
#pragma unroll
            for (int t = 0; t < 2; t++) {
                uint32_t r = (wm * 32 + t * 16 + lrow) * LDT + kb;
                ldsm_x4(ah[t], sb + r);
                ldsm_x4(al[t], sb + TILE + r);
            }
            // gate
            {
                uint32_t bh[2][4], bl[2][4];
#pragma unroll
                for (int gix = 0; gix < 2; gix++) {
                    uint32_t r = (wn * 32 + gix * 16 + lrow) * LDT + kb;
                    ldsm_x4(bh[gix], sb + 2 * TILE + r);
                    ldsm_x4(bl[gix], sb + 3 * TILE + r);
                }
#pragma unroll
                for (int t = 0; t < 2; t++)
#pragma unroll
                    for (int nt = 0; nt < 4; nt++) {
                        int gix = nt >> 1, sub = nt & 1;
                        mma16816(cg[t][nt], ah[t], bh[gix][sub], bh[gix][sub + 2]);
                        mma16816(cg[t][nt], ah[t], bl[gix][sub], bl[gix][sub + 2]);
                        mma16816(cg[t][nt], al[t], bh[gix][sub], bh[gix][sub + 2]);
                    }
            }
            // up
            {
                uint32_t bh[2][4], bl[2][4];
#pragma unroll
                for (int gix = 0; gix < 2; gix++) {
                    uint32_t r = (wn * 32 + gix * 16 + lrow) * LDT + kb;
                    ldsm_x4(bh[gix], sb + 4 * TILE + r);
                    ldsm_x4(bl[gix], sb + 5 * TILE + r);
                }
#pragma unroll
                for (int t = 0; t < 2; t++)
#pragma unroll
                    for (int nt = 0; nt < 4; nt++) {
                        int gix = nt >> 1, sub = nt & 1;
                        mma16816(cu[t][nt], ah[t], bh[gix][sub], bh[gix][sub + 2]);
                        mma16816(cu[t][nt], ah[t], bl[gix][sub], bl[gix][sub + 2]);
                        mma16816(cu[t][nt], al[t], bh[gix][sub], bh[gix][sub + 2]);
                    }
            }
        }
        __syncthreads();
        if (c + 2 < G1_NCH) load_chunk(c + 2, s);
    }

    // epilogue: SwiGLU, split to bf16 hi/lo, store to g_h
#pragma unroll
    for (int t = 0; t < 2; t++) {
#pragma unroll
        for (int jp = 0; jp < 2; jp++) {
            int crow = c0 + wm * 32 + t * 16 + (lane >> 2) + jp * 8;
            if (crow >= cnt) continue;
            size_t rowbase = ((size_t)e * CAP + crow) * NDIM + n0 + wn * 32;
#pragma unroll
            for (int nt = 0; nt < 4; nt++) {
                float g0 = fminf(cg[t][nt][jp * 2],     10.0f);
                float g1 = fminf(cg[t][nt][jp * 2 + 1], 10.0f);
                float u0 = fminf(fmaxf(cu[t][nt][jp * 2],     -10.0f), 10.0f);
                float u1 = fminf(fmaxf(cu[t][nt][jp * 2 + 1], -10.0f), 10.0f);
                float r0 = (g0 / (1.0f + __expf(-g0))) * u0;
                float r1 = (g1 / (1.0f + __expf(-g1))) * u1;
                __nv_bfloat162 hh, ll;
                split2(r0, r1, hh, ll);
                int ncol = nt * 8 + (lane & 3) * 2;
                *(__nv_bfloat162*)(g_h_hi + rowbase + ncol) = hh;
                *(__nv_bfloat162*)(g_h_lo + rowbase + ncol) = ll;
            }
        }
    }
}

// ---------------- GEMM2: down projection ----------------
// stage: AH AL BH BL, each TILE -> 73728 B/stage, 3 stages
#define G2_STAGE (4 * TILE)
#define G2_SMEM  (3 * G2_STAGE)
#define G2_NCH   (NDIM / 64)   // 22

__global__ __launch_bounds__(512, 1) void gemm2_kernel() {
    const int e   = blockIdx.z;
    const int cnt = g_counts[e];
    const int c0  = blockIdx.y * 128;
    if (c0 >= cnt) return;
    const int k0  = blockIdx.x * 128;
    const int tid = threadIdx.x;

    extern __shared__ char smem[];
    const uint32_t sb0 = smem_u32(smem);

    const int w    = tid >> 5;
    const int lane = tid & 31;
    const int wm   = w & 3;      // 32-row band
    const int wn   = w >> 2;     // 32-col group

    const __nv_bfloat16* aH = g_h_hi + ((size_t)e * CAP + c0) * NDIM;
    const __nv_bfloat16* aL = g_h_lo + ((size_t)e * CAP + c0) * NDIM;
    const __nv_bfloat16* bH = g_dw_hi + ((size_t)e * KDIM + k0) * NDIM;
    const __nv_bfloat16* bL = g_dw_lo + ((size_t)e * KDIM + k0) * NDIM;

    auto load_chunk = [&](int kc, int st) {
        uint32_t sb = sb0 + st * G2_STAGE;
        int ko = kc * 64;
        load_tile(sb + 0 * TILE, aH + ko, NDIM, tid);
        load_tile(sb + 1 * TILE, aL + ko, NDIM, tid);
        load_tile(sb + 2 * TILE, bH + ko, NDIM, tid);
        load_tile(sb + 3 * TILE, bL + ko, NDIM, tid);
        CPC();
    };

    float acc[2][4][4];
#pragma unroll
    for (int t = 0; t < 2; t++)
#pragma unroll
        for (int nt = 0; nt < 4; nt++)
#pragma unroll
            for (int j = 0; j < 4; j++) acc[t][nt][j] = 0.f;

    const int lrow  = lane & 15;
    const int lkoff = (lane >> 4) * 16;

    load_chunk(0, 0);
    load_chunk(1, 1);

    for (int c = 0; c < G2_NCH; c++) {
        const int s = c % 3;
        if (c + 2 < G2_NCH) { CPW1(); } else { CPW0(); }
        __syncthreads();
        if (c + 2 < G2_NCH) load_chunk(c + 2, (c + 2) % 3);

        const uint32_t sb = sb0 + s * G2_STAGE;
#pragma unroll
        for (int kk = 0; kk < 4; kk++) {
            const uint32_t kb = kk * 32 + lkoff;
            uint32_t ah[2][4], al[2][4];
#pragma unroll
            for (int t = 0; t < 2; t++) {
                uint32_t r = (wm * 32 + t * 16 + lrow) * LDT + kb;
                ldsm_x4(ah[t], sb + r);
                ldsm_x4(al[t], sb + TILE + r);
            }
            uint32_t bh[2][4], bl[2][4];
#pragma unroll
            for (int gix = 0; gix < 2; gix++) {
                uint32_t r = (wn * 32 + gix * 16 + lrow) * LDT + kb;
                ldsm_x4(bh[gix], sb + 2 * TILE + r);
                ldsm_x4(bl[gix], sb + 3 * TILE + r);
            }
#pragma unroll
            for (int t = 0; t < 2; t++)
#pragma unroll
                for (int nt = 0; nt < 4; nt++) {
                    int gix = nt >> 1, sub = nt & 1;
                    mma16816(acc[t][nt], ah[t], bh[gix][sub], bh[gix][sub + 2]);
                    mma16816(acc[t][nt], ah[t], bl[gix][sub], bl[gix][sub + 2]);
                    mma16816(acc[t][nt], al[t], bh[gix][sub], bh[gix][sub + 2]);
                }
        }
    }

    // epilogue: fp32 store to g_d
#pragma unroll
    for (int t = 0; t < 2; t++) {
#pragma unroll
        for (int jp = 0; jp < 2; jp++) {
            int crow = c0 + wm * 32 + t * 16 + (lane >> 2) + jp * 8;
            if (crow >= cnt) continue;
            float* dst = g_d + ((size_t)e * CAP + crow) * KDIM + k0 + wn * 32;
#pragma unroll
            for (int nt = 0; nt < 4; nt++) {
                float2 v;
                v.x = acc[t][nt][jp * 2];
                v.y = acc[t][nt][jp * 2 + 1];
                *(float2*)(dst + nt * 8 + (lane & 3) * 2) = v;
            }
        }
    }
}

// ---------------- combine ----------------
__global__ void combine_kernel(const int* __restrict__ idx,
                               const float* __restrict__ gate,
                               float* __restrict__ out)
{
    const int t = blockIdx.x;
    const int e0 = idx[2 * t], e1 = idx[2 * t + 1];
    const float w0 = gate[2 * t], w1 = gate[2 * t + 1];
    const int p0 = g_pos[2 * t], p1 = g_pos[2 * t + 1];
    const float* d0 = g_d + ((size_t)e0 * CAP + p0) * KDIM;
    const float* d1 = g_d + ((size_t)e1 * CAP + p1) * KDIM;
    float* o = out + (size_t)t * KDIM;

    for (int k = threadIdx.x * 4; k < KDIM; k += blockDim.x * 4) {
        float4 a = *(const float4*)(d0 + k);
        float4 b = *(const float4*)(d1 + k);
        float4 r;
        r.x = w0 * a.x + w1 * b.x;
        r.y = w0 * a.y + w1 * b.y;
        r.z = w0 * a.z + w1 * b.z;
        r.w = w0 * a.w + w1 * b.w;
        *(float4*)(o + k) = r;
    }
}

// ---------------- launch ----------------
extern "C" void kernel_launch(void* const* d_in, const int* in_sizes, int n_in,
                              void* d_out, int out_size)
{
    const float* X    = (const float*)d_in[0];  // flat_h      (M,K)
    const int*   idx  = (const int*)  d_in[1];  // flat_idx    (M,TOPK)
    const float* gate = (const float*)d_in[2];  // flat_gate   (M,TOPK)
    const float* GW   = (const float*)d_in[3];  // gate_weight (E,N,K)
    const float* UW   = (const float*)d_in[4];  // up_weight   (E,N,K)
    const float* DW   = (const float*)d_in[5];  // down_weight (E,K,N)
    float* out = (float*)d_out;

    cudaFuncSetAttribute(gemm1_kernel, cudaFuncAttributeMaxDynamicSharedMemorySize, G1_SMEM);
    cudaFuncSetAttribute(gemm2_kernel, cudaFuncAttributeMaxDynamicSharedMemorySize, G2_SMEM);

    route_kernel<<<1, 256>>>(idx);
    convert_all_kernel<<<4096, 256>>>((const float4*)GW, (const float4*)UW,
                                      (const float4*)DW);
    dispatch_kernel<<<dim3(CAP, NE), 256>>>(X);

    dim3 g1(NDIM / 128, CAP / 128, NE);   // (11, 8, 8)
    gemm1_kernel<<<g1, 512, G1_SMEM>>>();

    dim3 g2(KDIM / 128, CAP / 128, NE);   // (16, 8, 8)
    gemm2_kernel<<<g2, 512, G2_SMEM>>>();

    combine_kernel<<<MTOK, 256>>>(idx, gate, out);
}

// round 8
// speedup vs baseline: 2.9590x; 1.4091x over previous
#include <cuda_runtime.h>
#include <cuda_fp16.h>
#include <math.h>
#include <stdint.h>

#define NE      8
#define TOPK    2
#define MTOK    2048
#define KDIM    2048
#define NDIM    1408
#define CAP     1024
#define RROWS   (MTOK * TOPK)

// ---------------- scratch (device globals; no allocations) ----------------
__device__ int   g_counts[NE];
__device__ int   g_tok[NE * CAP];
__device__ int   g_pos[RROWS];
__device__ __half g_a_hi[(size_t)NE * CAP * KDIM];
__device__ __half g_a_lo[(size_t)NE * CAP * KDIM];
__device__ __half g_gw[(size_t)NE * NDIM * KDIM];
__device__ __half g_uw[(size_t)NE * NDIM * KDIM];
__device__ __half g_dw[(size_t)NE * KDIM * NDIM];
__device__ __half g_h_hi[(size_t)NE * CAP * NDIM];
__device__ __half g_h_lo[(size_t)NE * CAP * NDIM];
__device__ float g_d[(size_t)NE * CAP * KDIM];

// ---------------- helpers ----------------
__device__ __forceinline__ uint32_t smem_u32(const void* p) {
    return (uint32_t)__cvta_generic_to_shared(p);
}

#define CPA(dst, src) \
    asm volatile("cp.async.cg.shared.global [%0], [%1], 16;" :: "r"(dst), "l"(src) : "memory")
#define CPC()  asm volatile("cp.async.commit_group;" ::: "memory")
#define CPW1() asm volatile("cp.async.wait_group 1;" ::: "memory")
#define CPW0() asm volatile("cp.async.wait_group 0;" ::: "memory")

__device__ __forceinline__ void ldsm_x4(uint32_t* r, uint32_t a) {
    asm volatile("ldmatrix.sync.aligned.m8n8.x4.shared.b16 {%0,%1,%2,%3}, [%4];"
        : "=r"(r[0]), "=r"(r[1]), "=r"(r[2]), "=r"(r[3]) : "r"(a));
}

__device__ __forceinline__ void mma16816(float* c, const uint32_t* a,
                                         uint32_t b0, uint32_t b1) {
    asm volatile(
        "mma.sync.aligned.m16n8k16.row.col.f32.f16.f16.f32 "
        "{%0,%1,%2,%3}, {%4,%5,%6,%7}, {%8,%9}, {%0,%1,%2,%3};"
        : "+f"(c[0]), "+f"(c[1]), "+f"(c[2]), "+f"(c[3])
        : "r"(a[0]), "r"(a[1]), "r"(a[2]), "r"(a[3]), "r"(b0), "r"(b1));
}

// fp16 hi/lo split of two floats
__device__ __forceinline__ void split2h(float a, float b,
                                        __half2& hi, __half2& lo) {
    __half ha = __float2half_rn(a);
    __half hb = __float2half_rn(b);
    hi = __halves2half2(ha, hb);
    lo = __halves2half2(__float2half_rn(a - __half2float(ha)),
                        __float2half_rn(b - __half2float(hb)));
}

// padded tile row: 64 fp16 payload + 8 pad = 72 elems = 144 bytes
#define LDT   144
#define TILE  18432      // 128 rows * 144 B

// ---------------- routing ----------------
__global__ void route_kernel(const int* __restrict__ idx) {
    __shared__ int scnt[NE];
    int tid = threadIdx.x;
    if (tid < NE) scnt[tid] = 0;
    __syncthreads();
    for (int r = tid; r < RROWS; r += blockDim.x) {
        int e = idx[r];
        int p = atomicAdd(&scnt[e], 1);
        g_pos[r] = p;
        if (p < CAP) g_tok[e * CAP + p] = r >> 1;
    }
    __syncthreads();
    if (tid < NE) g_counts[tid] = scnt[tid];
}

// ---------------- fused weight conversion (single fp16, all 3 tensors) ----------------
#define WQ ((NE * NDIM * KDIM) / 4)   // float4 count per weight tensor
__global__ void convert_all_kernel(const float4* __restrict__ GW,
                                   const float4* __restrict__ UW,
                                   const float4* __restrict__ DW) {
    for (int i = blockIdx.x * blockDim.x + threadIdx.x; i < 3 * WQ;
         i += gridDim.x * blockDim.x) {
        const float4* s;
        __half2* dh;
        int j;
        if (i < WQ)          { j = i;          s = GW; dh = (__half2*)g_gw; }
        else if (i < 2 * WQ) { j = i - WQ;     s = UW; dh = (__half2*)g_uw; }
        else                 { j = i - 2 * WQ; s = DW; dh = (__half2*)g_dw; }
        float4 v = s[j];
        dh[2 * j]     = __halves2half2(__float2half_rn(v.x), __float2half_rn(v.y));
        dh[2 * j + 1] = __halves2half2(__float2half_rn(v.z), __float2half_rn(v.w));
    }
}

// ---------------- dispatch: gather tokens into (E,C,K) fp16 hi/lo ----------------
__global__ void dispatch_kernel(const float* __restrict__ X) {
    int e = blockIdx.y, slot = blockIdx.x;
    if (slot >= g_counts[e]) return;
    int tok = g_tok[e * CAP + slot];
    const float4* src = (const float4*)(X + (size_t)tok * KDIM);
    __half2* dh = (__half2*)(g_a_hi + ((size_t)e * CAP + slot) * KDIM);
    __half2* dl = (__half2*)(g_a_lo + ((size_t)e * CAP + slot) * KDIM);
    for (int q = threadIdx.x; q < KDIM / 4; q += blockDim.x) {
        float4 v = src[q];
        __half2 h0, l0, h1, l1;
        split2h(v.x, v.y, h0, l0);
        split2h(v.z, v.w, h1, l1);
        dh[2 * q] = h0; dh[2 * q + 1] = h1;
        dl[2 * q] = l0; dl[2 * q + 1] = l1;
    }
}

// ---------------- tile loader: 128 rows x 64 fp16, rows padded to 144B ----------------
// 512 threads: 2 iterations cover 1024 16B transfers
__device__ __forceinline__ void load_tile(uint32_t dst, const __half* src,
                                          int ld_src, int tid) {
#pragma unroll
    for (int i = 0; i < 2; i++) {
        int idx = i * 512 + tid;
        int row = idx >> 3;
        int c   = idx & 7;
        CPA(dst + row * LDT + c * 16,
            (const char*)src + (size_t)row * ld_src * 2 + c * 16);
    }
}

// ---------------- GEMM1: fused gate+up + SwiGLU ----------------
// stage: AH AL BG BU, each TILE -> 73728 B/stage, 3 stages
#define G1_STAGE (4 * TILE)
#define G1_SMEM  (3 * G1_STAGE)
#define G1_NCH   (KDIM / 64)   // 32

__global__ __launch_bounds__(512, 1) void gemm1_kernel() {
    const int e   = blockIdx.z;
    const int cnt = g_counts[e];
    const int c0  = blockIdx.y * 128;
    if (c0 >= cnt) return;
    const int n0  = blockIdx.x * 128;
    const int tid = threadIdx.x;

    extern __shared__ char smem[];
    const uint32_t sb0 = smem_u32(smem);

    const int w    = tid >> 5;
    const int lane = tid & 31;
    const int wm   = w & 3;       // 32-row band (0..3)
    const int wn   = w >> 2;      // 32-col group (0..3)

    const __half* aH = g_a_hi + ((size_t)e * CAP + c0) * KDIM;
    const __half* aL = g_a_lo + ((size_t)e * CAP + c0) * KDIM;
    const __half* bG = g_gw + ((size_t)e * NDIM + n0) * KDIM;
    const __half* bU = g_uw + ((size_t)e * NDIM + n0) * KDIM;

    auto load_chunk = [&](int kc, int st) {
        uint32_t sb = sb0 + st * G1_STAGE;
        int ko = kc * 64;
        load_tile(sb + 0 * TILE, aH + ko, KDIM, tid);
        load_tile(sb + 1 * TILE, aL + ko, KDIM, tid);
        load_tile(sb + 2 * TILE, bG + ko, KDIM, tid);
        load_tile(sb + 3 * TILE, bU + ko, KDIM, tid);
        CPC();
    };

    float cg[2][4][4], cu[2][4][4];
#pragma unroll
    for (int t = 0; t < 2; t++)
#pragma unroll
        for (int nt = 0; nt < 4; nt++)
#pragma unroll
            for (int j = 0; j < 4; j++) { cg[t][nt][j] = 0.f; cu[t][nt][j] = 0.f; }

    const int lrow  = lane & 15;
    const int lkoff = (lane >> 4) * 16;

    load_chunk(0, 0);
    load_chunk(1, 1);

    for (int c = 0; c < G1_NCH; c++) {
        const int s = c % 3;
        if (c + 2 < G1_NCH) { CPW1(); } else { CPW0(); }
        __syncthreads();
        if (c + 2 < G1_NCH) load_chunk(c + 2, (c + 2) % 3);

        const uint32_t sb = sb0 + s * G1_STAGE;
#pragma unroll
        for (int kk = 0; kk < 4; kk++) {
            const uint32_t kb = kk * 32 + lkoff;
            uint32_t ah[2][4], al[2][4];
#pragma unroll
            for (int t = 0; t < 2; t++) {
                uint32_t r = (wm * 32 + t * 16 + lrow) * LDT + kb;
                ldsm_x4(ah[t], sb + r);
                ldsm_x4(al[t], sb + TILE + r);
            }
            uint32_t bg[2][4], bu[2][4];
#pragma unroll
            for (int gix = 0; gix < 2; gix++) {
                uint32_t r = (wn * 32 + gix * 16 + lrow) * LDT + kb;
                ldsm_x4(bg[gix], sb + 2 * TILE + r);
                ldsm_x4(bu[gix], sb + 3 * TILE + r);
            }
#pragma unroll
            for (int t = 0; t < 2; t++)
#pragma unroll
                for (int nt = 0; nt < 4; nt++) {
                    int gix = nt >> 1, sub = nt & 1;
                    mma16816(cg[t][nt], ah[t], bg[gix][sub], bg[gix][sub + 2]);
                    mma16816(cg[t][nt], al[t], bg[gix][sub], bg[gix][sub + 2]);
                    mma16816(cu[t][nt], ah[t], bu[gix][sub], bu[gix][sub + 2]);
                    mma16816(cu[t][nt], al[t], bu[gix][sub], bu[gix][sub + 2]);
                }
        }
    }

    // epilogue: SwiGLU, split to fp16 hi/lo, store to g_h
#pragma unroll
    for (int t = 0; t < 2; t++) {
#pragma unroll
        for (int jp = 0; jp < 2; jp++) {
            int crow = c0 + wm * 32 + t * 16 + (lane >> 2) + jp * 8;
            if (crow >= cnt) continue;
            size_t rowbase = ((size_t)e * CAP + crow) * NDIM + n0 + wn * 32;
#pragma unroll
            for (int nt = 0; nt < 4; nt++) {
                float g0 = fminf(cg[t][nt][jp * 2],     10.0f);
                float g1 = fminf(cg[t][nt][jp * 2 + 1], 10.0f);
                float u0 = fminf(fmaxf(cu[t][nt][jp * 2],     -10.0f), 10.0f);
                float u1 = fminf(fmaxf(cu[t][nt][jp * 2 + 1], -10.0f), 10.0f);
                float r0 = (g0 / (1.0f + __expf(-g0))) * u0;
                float r1 = (g1 / (1.0f + __expf(-g1))) * u1;
                __half2 hh, ll;
                split2h(r0, r1, hh, ll);
                int ncol = nt * 8 + (lane & 3) * 2;
                *(__half2*)(g_h_hi + rowbase + ncol) = hh;
                *(__half2*)(g_h_lo + rowbase + ncol) = ll;
            }
        }
    }
}

// ---------------- GEMM2: down projection ----------------
// stage: AH AL B, each TILE -> 55296 B/stage, 3 stages
#define G2_STAGE (3 * TILE)
#define G2_SMEM  (3 * G2_STAGE)
#define G2_NCH   (NDIM / 64)   // 22

__global__ __launch_bounds__(512, 1) void gemm2_kernel() {
    const int e   = blockIdx.z;
    const int cnt = g_counts[e];
    const int c0  = blockIdx.y * 128;
    if (c0 >= cnt) return;
    const int k0  = blockIdx.x * 128;
    const int tid = threadIdx.x;

    extern __shared__ char smem[];
    const uint32_t sb0 = smem_u32(smem);

    const int w    = tid >> 5;
    const int lane = tid & 31;
    const int wm   = w & 3;      // 32-row band
    const int wn   = w >> 2;     // 32-col group

    const __half* aH = g_h_hi + ((size_t)e * CAP + c0) * NDIM;
    const __half* aL = g_h_lo + ((size_t)e * CAP + c0) * NDIM;
    const __half* bW = g_dw + ((size_t)e * KDIM + k0) * NDIM;

    auto load_chunk = [&](int kc, int st) {
        uint32_t sb = sb0 + st * G2_STAGE;
        int ko = kc * 64;
        load_tile(sb + 0 * TILE, aH + ko, NDIM, tid);
        load_tile(sb + 1 * TILE, aL + ko, NDIM, tid);
        load_tile(sb + 2 * TILE, bW + ko, NDIM, tid);
        CPC();
    };

    float acc[2][4][4];
#pragma unroll
    for (int t = 0; t < 2; t++)
#pragma unroll
        for (int nt = 0; nt < 4; nt++)
#pragma unroll
            for (int j = 0; j < 4; j++) acc[t][nt][j] = 0.f;

    const int lrow  = lane & 15;
    const int lkoff = (lane >> 4) * 16;

    load_chunk(0, 0);
    load_chunk(1, 1);

    for (int c = 0; c < G2_NCH; c++) {
        const int s = c % 3;
        if (c + 2 < G2_NCH) { CPW1(); } else { CPW0(); }
        __syncthreads();
        if (c + 2 < G2_NCH) load_chunk(c + 2, (c + 2) % 3);

        const uint32_t sb = sb0 + s * G2_STAGE;
#pragma unroll
        for (int kk = 0; kk < 4; kk++) {
            const uint32_t kb = kk * 32 + lkoff;
            uint32_t ah[2][4], al[2][4];
#pragma unroll
            for (int t = 0; t < 2; t++) {
                uint32_t r = (wm * 32 + t * 16 + lrow) * LDT + kb;
                ldsm_x4(ah[t], sb + r);
                ldsm_x4(al[t], sb + TILE + r);
            }
            uint32_t bh[2][4];
#pragma unroll
            for (int gix = 0; gix < 2; gix++) {
                uint32_t r = (wn * 32 + gix * 16 + lrow) * LDT + kb;
                ldsm_x4(bh[gix], sb + 2 * TILE + r);
            }
#pragma unroll
            for (int t = 0; t < 2; t++)
#pragma unroll
                for (int nt = 0; nt < 4; nt++) {
                    int gix = nt >> 1, sub = nt & 1;
                    mma16816(acc[t][nt], ah[t], bh[gix][sub], bh[gix][sub + 2]);
                    mma16816(acc[t][nt], al[t], bh[gix][sub], bh[gix][sub + 2]);
                }
        }
    }

    // epilogue: fp32 store to g_d
#pragma unroll
    for (int t = 0; t < 2; t++) {
#pragma unroll
        for (int jp = 0; jp < 2; jp++) {
            int crow = c0 + wm * 32 + t * 16 + (lane >> 2) + jp * 8;
            if (crow >= cnt) continue;
            float* dst = g_d + ((size_t)e * CAP + crow) * KDIM + k0 + wn * 32;
#pragma unroll
            for (int nt = 0; nt < 4; nt++) {
                float2 v;
                v.x = acc[t][nt][jp * 2];
                v.y = acc[t][nt][jp * 2 + 1];
                *(float2*)(dst + nt * 8 + (lane & 3) * 2) = v;
            }
        }
    }
}

// ---------------- combine ----------------
__global__ void combine_kernel(const int* __restrict__ idx,
                               const float* __restrict__ gate,
                               float* __restrict__ out)
{
    const int t = blockIdx.x;
    const int e0 = idx[2 * t], e1 = idx[2 * t + 1];
    const float w0 = gate[2 * t], w1 = gate[2 * t + 1];
    const int p0 = g_pos[2 * t], p1 = g_pos[2 * t + 1];
    const float* d0 = g_d + ((size_t)e0 * CAP + p0) * KDIM;
    const float* d1 = g_d + ((size_t)e1 * CAP + p1) * KDIM;
    float* o = out + (size_t)t * KDIM;

    for (int k = threadIdx.x * 4; k < KDIM; k += blockDim.x * 4) {
        float4 a = *(const float4*)(d0 + k);
        float4 b = *(const float4*)(d1 + k);
        float4 r;
        r.x = w0 * a.x + w1 * b.x;
        r.y = w0 * a.y + w1 * b.y;
        r.z = w0 * a.z + w1 * b.z;
        r.w = w0 * a.w + w1 * b.w;
        *(float4*)(o + k) = r;
    }
}

// ---------------- launch ----------------
extern "C" void kernel_launch(void* const* d_in, const int* in_sizes, int n_in,
                              void* d_out, int out_size)
{
    const float* X    = (const float*)d_in[0];  // flat_h      (M,K)
    const int*   idx  = (const int*)  d_in[1];  // flat_idx    (M,TOPK)
    const float* gate = (const float*)d_in[2];  // flat_gate   (M,TOPK)
    const float* GW   = (const float*)d_in[3];  // gate_weight (E,N,K)
    const float* UW   = (const float*)d_in[4];  // up_weight   (E,N,K)
    const float* DW   = (const float*)d_in[5];  // down_weight (E,K,N)
    float* out = (float*)d_out;

    cudaFuncSetAttribute(gemm1_kernel, cudaFuncAttributeMaxDynamicSharedMemorySize, G1_SMEM);
    cudaFuncSetAttribute(gemm2_kernel, cudaFuncAttributeMaxDynamicSharedMemorySize, G2_SMEM);

    route_kernel<<<1, 256>>>(idx);
    convert_all_kernel<<<4096, 256>>>((const float4*)GW, (const float4*)UW,
                                      (const float4*)DW);
    dispatch_kernel<<<dim3(CAP, NE), 256>>>(X);

    dim3 g1(NDIM / 128, CAP / 128, NE);   // (11, 8, 8)
    gemm1_kernel<<<g1, 512, G1_SMEM>>>();

    dim3 g2(KDIM / 128, CAP / 128, NE);   // (16, 8, 8)
    gemm2_kernel<<<g2, 512, G2_SMEM>>>();

    combine_kernel<<<MTOK, 256>>>(idx, gate, out);
}

// round 10
// speedup vs baseline: 3.4832x; 1.1772x over previous
#include <cuda_runtime.h>
#include <cuda_fp16.h>
#include <math.h>
#include <stdint.h>

#define NE      8
#define TOPK    2
#define MTOK    2048
#define KDIM    2048
#define NDIM    1408
#define CAP     1024
#define RROWS   (MTOK * TOPK)

#define NB1 (NDIM / 128)   // 11
#define NB2 (KDIM / 128)   // 16

// ---------------- scratch (device globals; no allocations) ----------------
__device__ int   g_counts[NE];
__device__ int   g_tok[NE * CAP];
__device__ int   g_pos[RROWS];
__device__ int   g_map1[NE * (CAP / 128) * NB1];   // 704
__device__ int   g_map2[NE * (CAP / 128) * NB2];   // 1024
__device__ int   g_n1, g_n2, g_ctr1, g_ctr2;
__device__ __half g_a_hi[(size_t)NE * CAP * KDIM];
__device__ __half g_a_lo[(size_t)NE * CAP * KDIM];
__device__ __half g_gw[(size_t)NE * NDIM * KDIM];
__device__ __half g_uw[(size_t)NE * NDIM * KDIM];
__device__ __half g_dw[(size_t)NE * KDIM * NDIM];
__device__ __half g_h[(size_t)NE * CAP * NDIM];
__device__ float g_d[(size_t)NE * CAP * KDIM];

// ---------------- helpers ----------------
__device__ __forceinline__ uint32_t smem_u32(const void* p) {
    return (uint32_t)__cvta_generic_to_shared(p);
}

#define CPA(dst, src) \
    asm volatile("cp.async.cg.shared.global [%0], [%1], 16;" :: "r"(dst), "l"(src) : "memory")
#define CPC()  asm volatile("cp.async.commit_group;" ::: "memory")
#define CPW1() asm volatile("cp.async.wait_group 1;" ::: "memory")
#define CPW0() asm volatile("cp.async.wait_group 0;" ::: "memory")

__device__ __forceinline__ void ldsm_x4(uint32_t* r, uint32_t a) {
    asm volatile("ldmatrix.sync.aligned.m8n8.x4.shared.b16 {%0,%1,%2,%3}, [%4];"
        : "=r"(r[0]), "=r"(r[1]), "=r"(r[2]), "=r"(r[3]) : "r"(a));
}

__device__ __forceinline__ void mma16816(float* c, const uint32_t* a,
                                         uint32_t b0, uint32_t b1) {
    asm volatile(
        "mma.sync.aligned.m16n8k16.row.col.f32.f16.f16.f32 "
        "{%0,%1,%2,%3}, {%4,%5,%6,%7}, {%8,%9}, {%0,%1,%2,%3};"
        : "+f"(c[0]), "+f"(c[1]), "+f"(c[2]), "+f"(c[3])
        : "r"(a[0]), "r"(a[1]), "r"(a[2]), "r"(a[3]), "r"(b0), "r"(b1));
}

__device__ __forceinline__ void split2h(float a, float b,
                                        __half2& hi, __half2& lo) {
    __half ha = __float2half_rn(a);
    __half hb = __float2half_rn(b);
    hi = __halves2half2(ha, hb);
    lo = __halves2half2(__float2half_rn(a - __half2float(ha)),
                        __float2half_rn(b - __half2float(hb)));
}

#define LDT   144
#define TILE  18432      // 128 rows * 144 B

// ---------------- routing + tile maps ----------------
__global__ void route_kernel(const int* __restrict__ idx) {
    __shared__ int scnt[NE];
    int tid = threadIdx.x;
    if (tid < NE) scnt[tid] = 0;
    __syncthreads();
    for (int r = tid; r < RROWS; r += blockDim.x) {
        int e = idx[r];
        int p = atomicAdd(&scnt[e], 1);
        g_pos[r] = p;
        if (p < CAP) g_tok[e * CAP + p] = r >> 1;
    }
    __syncthreads();
    if (tid < NE) g_counts[tid] = scnt[tid];
    if (tid == 0) {
        int n1 = 0, n2 = 0;
        for (int e = 0; e < NE; e++) {
            int nb = (scnt[e] + 127) >> 7;
            for (int cb = 0; cb < nb; cb++) {
                for (int x = 0; x < NB1; x++)
                    g_map1[n1++] = (e << 16) | (cb << 8) | x;
                for (int x = 0; x < NB2; x++)
                    g_map2[n2++] = (e << 16) | (cb << 8) | x;
            }
        }
        g_n1 = n1; g_n2 = n2;
        g_ctr1 = 0; g_ctr2 = 0;
    }
}

// ---------------- fused weight conversion ----------------
#define WQ ((NE * NDIM * KDIM) / 4)
__global__ void convert_all_kernel(const float4* __restrict__ GW,
                                   const float4* __restrict__ UW,
                                   const float4* __restrict__ DW) {
    for (int i = blockIdx.x * blockDim.x + threadIdx.x; i < 3 * WQ;
         i += gridDim.x * blockDim.x) {
        const float4* s;
        __half2* dh;
        int j;
        if (i < WQ)          { j = i;          s = GW; dh = (__half2*)g_gw; }
        else if (i < 2 * WQ) { j = i - WQ;     s = UW; dh = (__half2*)g_uw; }
        else                 { j = i - 2 * WQ; s = DW; dh = (__half2*)g_dw; }
        float4 v = s[j];
        dh[2 * j]     = __halves2half2(__float2half_rn(v.x), __float2half_rn(v.y));
        dh[2 * j + 1] = __halves2half2(__float2half_rn(v.z), __float2half_rn(v.w));
    }
}

// ---------------- dispatch ----------------
__global__ void dispatch_kernel(const float* __restrict__ X) {
    int e = blockIdx.y, slot = blockIdx.x;
    if (slot >= g_counts[e]) return;
    int tok = g_tok[e * CAP + slot];
    const float4* src = (const float4*)(X + (size_t)tok * KDIM);
    __half2* dh = (__half2*)(g_a_hi + ((size_t)e * CAP + slot) * KDIM);
    __half2* dl = (__half2*)(g_a_lo + ((size_t)e * CAP + slot) * KDIM);
    for (int q = threadIdx.x; q < KDIM / 4; q += blockDim.x) {
        float4 v = src[q];
        __half2 h0, l0, h1, l1;
        split2h(v.x, v.y, h0, l0);
        split2h(v.z, v.w, h1, l1);
        dh[2 * q] = h0; dh[2 * q + 1] = h1;
        dl[2 * q] = l0; dl[2 * q + 1] = l1;
    }
}

// ---------------- tile loader ----------------
__device__ __forceinline__ void load_tile(uint32_t dst, const __half* src,
                                          int ld_src, int tid) {
#pragma unroll
    for (int i = 0; i < 2; i++) {
        int idx = i * 512 + tid;
        int row = idx >> 3;
        int c   = idx & 7;
        CPA(dst + row * LDT + c * 16,
            (const char*)src + (size_t)row * ld_src * 2 + c * 16);
    }
}

// ---------------- GEMM1: persistent, fused gate+up + SwiGLU ----------------
// stage: AH AL BG BU -> 73728 B, 3 stages
#define G1_STAGE (4 * TILE)
#define G1_SMEM  (3 * G1_STAGE)
#define G1_NCH   (KDIM / 64)   // 32

__global__ __launch_bounds__(512, 1) void gemm1_kernel() {
    extern __shared__ char smem[];
    const uint32_t sb0 = smem_u32(smem);
    __shared__ int s_tile;

    const int tid  = threadIdx.x;
    const int w    = tid >> 5;
    const int lane = tid & 31;
    const int wm   = w & 3;
    const int wn   = w >> 2;
    const int lrow  = lane & 15;
    const int lkoff = (lane >> 4) * 16;
    const int ntile = g_n1;

    for (;;) {
        if (tid == 0) s_tile = atomicAdd(&g_ctr1, 1);
        __syncthreads();
        const int t = s_tile;
        if (t >= ntile) break;
        const int m   = g_map1[t];
        const int e   = m >> 16;
        const int c0  = ((m >> 8) & 0xFF) * 128;
        const int n0  = (m & 0xFF) * 128;
        const int cnt = g_counts[e];

        const __half* aH = g_a_hi + ((size_t)e * CAP + c0) * KDIM;
        const __half* aL = g_a_lo + ((size_t)e * CAP + c0) * KDIM;
        const __half* bG = g_gw + ((size_t)e * NDIM + n0) * KDIM;
        const __half* bU = g_uw + ((size_t)e * NDIM + n0) * KDIM;

        auto load_chunk = [&](int kc, int st) {
            uint32_t sb = sb0 + st * G1_STAGE;
            int ko = kc * 64;
            load_tile(sb + 0 * TILE, aH + ko, KDIM, tid);
            load_tile(sb + 1 * TILE, aL + ko, KDIM, tid);
            load_tile(sb + 2 * TILE, bG + ko, KDIM, tid);
            load_tile(sb + 3 * TILE, bU + ko, KDIM, tid);
            CPC();
        };

        float cg[2][4][4], cu[2][4][4];
#pragma unroll
        for (int tt = 0; tt < 2; tt++)
#pragma unroll
            for (int nt = 0; nt < 4; nt++)
#pragma unroll
                for (int j = 0; j < 4; j++) { cg[tt][nt][j] = 0.f; cu[tt][nt][j] = 0.f; }

        load_chunk(0, 0);
        load_chunk(1, 1);

        for (int c = 0; c < G1_NCH; c++) {
            const int s = c % 3;
            if (c + 2 < G1_NCH) { CPW1(); } else { CPW0(); }
            __syncthreads();
            if (c + 2 < G1_NCH) load_chunk(c + 2, (c + 2) % 3);

            const uint32_t sb = sb0 + s * G1_STAGE;
#pragma unroll
            for (int kk = 0; kk < 4; kk++) {
                const uint32_t kb = kk * 32 + lkoff;
                uint32_t ah[2][4], al[2][4];
#pragma unroll
                for (int tt = 0; tt < 2; tt++) {
                    uint32_t r = (wm * 32 + tt * 16 + lrow) * LDT + kb;
                    ldsm_x4(ah[tt], sb + r);
                    ldsm_x4(al[tt], sb + TILE + r);
                }
                uint32_t bg[2][4], bu[2][4];
#pragma unroll
                for (int gix = 0; gix < 2; gix++) {
                    uint32_t r = (wn * 32 + gix * 16 + lrow) * LDT + kb;
                    ldsm_x4(bg[gix], sb + 2 * TILE + r);
                    ldsm_x4(bu[gix], sb + 3 * TILE + r);
                }
#pragma unroll
                for (int tt = 0; tt < 2; tt++)
#pragma unroll
                    for (int nt = 0; nt < 4; nt++) {
                        int gix = nt >> 1, sub = nt & 1;
                        mma16816(cg[tt][nt], ah[tt], bg[gix][sub], bg[gix][sub + 2]);
                        mma16816(cg[tt][nt], al[tt], bg[gix][sub], bg[gix][sub + 2]);
                        mma16816(cu[tt][nt], ah[tt], bu[gix][sub], bu[gix][sub + 2]);
                        mma16816(cu[tt][nt], al[tt], bu[gix][sub], bu[gix][sub + 2]);
                    }
            }
        }

        // epilogue: SwiGLU -> single fp16 h
#pragma unroll
        for (int tt = 0; tt < 2; tt++) {
#pragma unroll
            for (int jp = 0; jp < 2; jp++) {
                int crow = c0 + wm * 32 + tt * 16 + (lane >> 2) + jp * 8;
                if (crow >= cnt) continue;
                size_t rowbase = ((size_t)e * CAP + crow) * NDIM + n0 + wn * 32;
#pragma unroll
                for (int nt = 0; nt < 4; nt++) {
                    float g0 = fminf(cg[tt][nt][jp * 2],     10.0f);
                    float g1 = fminf(cg[tt][nt][jp * 2 + 1], 10.0f);
                    float u0 = fminf(fmaxf(cu[tt][nt][jp * 2],     -10.0f), 10.0f);
                    float u1 = fminf(fmaxf(cu[tt][nt][jp * 2 + 1], -10.0f), 10.0f);
                    float r0 = (g0 / (1.0f + __expf(-g0))) * u0;
                    float r1 = (g1 / (1.0f + __expf(-g1))) * u1;
                    int ncol = nt * 8 + (lane & 3) * 2;
                    *(__half2*)(g_h + rowbase + ncol) = __floats2half2_rn(r0, r1);
                }
            }
        }
    }
}

// ---------------- GEMM2: persistent, plain fp16 down projection ----------------
// stage: A B -> 36864 B, 3 stages (110 KB, 2 CTAs/SM)
#define G2_STAGE (2 * TILE)
#define G2_SMEM  (3 * G2_STAGE)
#define G2_NCH   (NDIM / 64)   // 22

__global__ __launch_bounds__(512, 2) void gemm2_kernel() {
    extern __shared__ char smem[];
    const uint32_t sb0 = smem_u32(smem);
    __shared__ int s_tile;

    const int tid  = threadIdx.x;
    const int w    = tid >> 5;
    const int lane = tid & 31;
    const int wm   = w & 3;
    const int wn   = w >> 2;
    const int lrow  = lane & 15;
    const int lkoff = (lane >> 4) * 16;
    const int ntile = g_n2;

    for (;;) {
        if (tid == 0) s_tile = atomicAdd(&g_ctr2, 1);
        __syncthreads();
        const int t = s_tile;
        if (t >= ntile) break;
        const int m   = g_map2[t];
        const int e   = m >> 16;
        const int c0  = ((m >> 8) & 0xFF) * 128;
        const int k0  = (m & 0xFF) * 128;
        const int cnt = g_counts[e];

        const __half* aT = g_h + ((size_t)e * CAP + c0) * NDIM;
        const __half* bW = g_dw + ((size_t)e * KDIM + k0) * NDIM;

        auto load_chunk = [&](int kc, int st) {
            uint32_t sb = sb0 + st * G2_STAGE;
            int ko = kc * 64;
            load_tile(sb + 0 * TILE, aT + ko, NDIM, tid);
            load_tile(sb + 1 * TILE, bW + ko, NDIM, tid);
            CPC();
        };

        float acc[2][4][4];
#pragma unroll
        for (int tt = 0; tt < 2; tt++)
#pragma unroll
            for (int nt = 0; nt < 4; nt++)
#pragma unroll
                for (int j = 0; j < 4; j++) acc[tt][nt][j] = 0.f;

        load_chunk(0, 0);
        load_chunk(1, 1);

        for (int c = 0; c < G2_NCH; c++) {
            const int s = c % 3;
            if (c + 2 < G2_NCH) { CPW1(); } else { CPW0(); }
            __syncthreads();
            if (c + 2 < G2_NCH) load_chunk(c + 2, (c + 2) % 3);

            const uint32_t sb = sb0 + s * G2_STAGE;
#pragma unroll
            for (int kk = 0; kk < 4; kk++) {
                const uint32_t kb = kk * 32 + lkoff;
                uint32_t ah[2][4];
#pragma unroll
                for (int tt = 0; tt < 2; tt++) {
                    uint32_t r = (wm * 32 + tt * 16 + lrow) * LDT + kb;
                    ldsm_x4(ah[tt], sb + r);
                }
                uint32_t bh[2][4];
#pragma unroll
                for (int gix = 0; gix < 2; gix++) {
                    uint32_t r = (wn * 32 + gix * 16 + lrow) * LDT + kb;
                    ldsm_x4(bh[gix], sb + TILE + r);
                }
#pragma unroll
                for (int tt = 0; tt < 2; tt++)
#pragma unroll
                    for (int nt = 0; nt < 4; nt++) {
                        int gix = nt >> 1, sub = nt & 1;
                        mma16816(acc[tt][nt], ah[tt], bh[gix][sub], bh[gix][sub + 2]);
                    }
            }
        }

        // epilogue: fp32 store to g_d
#pragma unroll
        for (int tt = 0; tt < 2; tt++) {
#pragma unroll
            for (int jp = 0; jp < 2; jp++) {
                int crow = c0 + wm * 32 + tt * 16 + (lane >> 2) + jp * 8;
                if (crow >= cnt) continue;
                float* dst = g_d + ((size_t)e * CAP + crow) * KDIM + k0 + wn * 32;
#pragma unroll
                for (int nt = 0; nt < 4; nt++) {
                    float2 v;
                    v.x = acc[tt][nt][jp * 2];
                    v.y = acc[tt][nt][jp * 2 + 1];
                    *(float2*)(dst + nt * 8 + (lane & 3) * 2) = v;
                }
            }
        }
    }
}

// ---------------- combine ----------------
__global__ void combine_kernel(const int* __restrict__ idx,
                               const float* __restrict__ gate,
                               float* __restrict__ out)
{
    const int t = blockIdx.x;
    const int e0 = idx[2 * t], e1 = idx[2 * t + 1];
    const float w0 = gate[2 * t], w1 = gate[2 * t + 1];
    const int p0 = g_pos[2 * t], p1 = g_pos[2 * t + 1];
    const float* d0 = g_d + ((size_t)e0 * CAP + p0) * KDIM;
    const float* d1 = g_d + ((size_t)e1 * CAP + p1) * KDIM;
    float* o = out + (size_t)t * KDIM;

    for (int k = threadIdx.x * 4; k < KDIM; k += blockDim.x * 4) {
        float4 a = *(const float4*)(d0 + k);
        float4 b = *(const float4*)(d1 + k);
        float4 r;
        r.x = w0 * a.x + w1 * b.x;
        r.y = w0 * a.y + w1 * b.y;
        r.z = w0 * a.z + w1 * b.z;
        r.w = w0 * a.w + w1 * b.w;
        *(float4*)(o + k) = r;
    }
}

// ---------------- launch ----------------
extern "C" void kernel_launch(void* const* d_in, const int* in_sizes, int n_in,
                              void* d_out, int out_size)
{
    const float* X    = (const float*)d_in[0];
    const int*   idx  = (const int*)  d_in[1];
    const float* gate = (const float*)d_in[2];
    const float* GW   = (const float*)d_in[3];
    const float* UW   = (const float*)d_in[4];
    const float* DW   = (const float*)d_in[5];
    float* out = (float*)d_out;

    cudaFuncSetAttribute(gemm1_kernel, cudaFuncAttributeMaxDynamicSharedMemorySize, G1_SMEM);
    cudaFuncSetAttribute(gemm2_kernel, cudaFuncAttributeMaxDynamicSharedMemorySize, G2_SMEM);

    route_kernel<<<1, 256>>>(idx);
    convert_all_kernel<<<4096, 256>>>((const float4*)GW, (const float4*)UW,
                                      (const float4*)DW);
    dispatch_kernel<<<dim3(CAP, NE), 256>>>(X);

    gemm1_kernel<<<148, 512, G1_SMEM>>>();
    gemm2_kernel<<<296, 512, G2_SMEM>>>();

    combine_kernel<<<MTOK, 256>>>(idx, gate, out);
}

// round 12
// speedup vs baseline: 4.8566x; 1.3943x over previous
#include <cuda_runtime.h>
#include <cuda_fp16.h>
#include <math.h>
#include <stdint.h>

#define NE      8
#define TOPK    2
#define MTOK    2048
#define KDIM    2048
#define NDIM    1408
#define CAP     1024
#define RROWS   (MTOK * TOPK)

#define NB1 (NDIM / 128)   // 11
#define NB2 (KDIM / 128)   // 16

// ---------------- scratch (device globals; no allocations) ----------------
__device__ int   g_counts[NE];
__device__ int   g_tok[NE * CAP];
__device__ int   g_pos[RROWS];
__device__ int   g_map1[NE * (CAP / 128) * NB1];   // 704
__device__ int   g_map2[NE * (CAP / 128) * NB2];   // 1024
__device__ int   g_n1, g_n2, g_ctr1, g_ctr2;
__device__ __half g_a[(size_t)NE * CAP * KDIM];
__device__ __half g_gw[(size_t)NE * NDIM * KDIM];
__device__ __half g_uw[(size_t)NE * NDIM * KDIM];
__device__ __half g_dw[(size_t)NE * KDIM * NDIM];
__device__ __half g_h[(size_t)NE * CAP * NDIM];
__device__ float g_d[(size_t)NE * CAP * KDIM];

// ---------------- helpers ----------------
__device__ __forceinline__ uint32_t smem_u32(const void* p) {
    return (uint32_t)__cvta_generic_to_shared(p);
}

#define CPA(dst, src) \
    asm volatile("cp.async.cg.shared.global [%0], [%1], 16;" :: "r"(dst), "l"(src) : "memory")
#define CPC()  asm volatile("cp.async.commit_group;" ::: "memory")
#define CPW1() asm volatile("cp.async.wait_group 1;" ::: "memory")
#define CPW0() asm volatile("cp.async.wait_group 0;" ::: "memory")

__device__ __forceinline__ void ldsm_x4(uint32_t* r, uint32_t a) {
    asm volatile("ldmatrix.sync.aligned.m8n8.x4.shared.b16 {%0,%1,%2,%3}, [%4];"
        : "=r"(r[0]), "=r"(r[1]), "=r"(r[2]), "=r"(r[3]) : "r"(a));
}

__device__ __forceinline__ void mma16816(float* c, const uint32_t* a,
                                         uint32_t b0, uint32_t b1) {
    asm volatile(
        "mma.sync.aligned.m16n8k16.row.col.f32.f16.f16.f32 "
        "{%0,%1,%2,%3}, {%4,%5,%6,%7}, {%8,%9}, {%0,%1,%2,%3};"
        : "+f"(c[0]), "+f"(c[1]), "+f"(c[2]), "+f"(c[3])
        : "r"(a[0]), "r"(a[1]), "r"(a[2]), "r"(a[3]), "r"(b0), "r"(b1));
}

#define LDT   144
#define TILE  18432      // 128 rows * 144 B

// ---------------- routing + tile maps ----------------
__global__ void route_kernel(const int* __restrict__ idx) {
    __shared__ int scnt[NE];
    int tid = threadIdx.x;
    if (tid < NE) scnt[tid] = 0;
    __syncthreads();
    for (int r = tid; r < RROWS; r += blockDim.x) {
        int e = idx[r];
        int p = atomicAdd(&scnt[e], 1);
        g_pos[r] = p;
        if (p < CAP) g_tok[e * CAP + p] = r >> 1;
    }
    __syncthreads();
    if (tid < NE) g_counts[tid] = scnt[tid];
    if (tid == 0) {
        int n1 = 0, n2 = 0;
        for (int e = 0; e < NE; e++) {
            int nb = (scnt[e] + 127) >> 7;
            for (int cb = 0; cb < nb; cb++) {
                for (int x = 0; x < NB1; x++)
                    g_map1[n1++] = (e << 16) | (cb << 8) | x;
                for (int x = 0; x < NB2; x++)
                    g_map2[n2++] = (e << 16) | (cb << 8) | x;
            }
        }
        g_n1 = n1; g_n2 = n2;
        g_ctr1 = 0; g_ctr2 = 0;
    }
}

// ---------------- fused weight conversion ----------------
#define WQ ((NE * NDIM * KDIM) / 4)
__global__ void convert_all_kernel(const float4* __restrict__ GW,
                                   const float4* __restrict__ UW,
                                   const float4* __restrict__ DW) {
    for (int i = blockIdx.x * blockDim.x + threadIdx.x; i < 3 * WQ;
         i += gridDim.x * blockDim.x) {
        const float4* s;
        __half2* dh;
        int j;
        if (i < WQ)          { j = i;          s = GW; dh = (__half2*)g_gw; }
        else if (i < 2 * WQ) { j = i - WQ;     s = UW; dh = (__half2*)g_uw; }
        else                 { j = i - 2 * WQ; s = DW; dh = (__half2*)g_dw; }
        float4 v = s[j];
        dh[2 * j]     = __halves2half2(__float2half_rn(v.x), __float2half_rn(v.y));
        dh[2 * j + 1] = __halves2half2(__float2half_rn(v.z), __float2half_rn(v.w));
    }
}

// ---------------- dispatch: gather tokens into (E,C,K) fp16 ----------------
__global__ void dispatch_kernel(const float* __restrict__ X) {
    int e = blockIdx.y, slot = blockIdx.x;
    if (slot >= g_counts[e]) return;
    int tok = g_tok[e * CAP + slot];
    const float4* src = (const float4*)(X + (size_t)tok * KDIM);
    __half2* dh = (__half2*)(g_a + ((size_t)e * CAP + slot) * KDIM);
    for (int q = threadIdx.x; q < KDIM / 4; q += blockDim.x) {
        float4 v = src[q];
        dh[2 * q]     = __floats2half2_rn(v.x, v.y);
        dh[2 * q + 1] = __floats2half2_rn(v.z, v.w);
    }
}

// ---------------- tile loader ----------------
__device__ __forceinline__ void load_tile(uint32_t dst, const __half* src,
                                          int ld_src, int tid) {
#pragma unroll
    for (int i = 0; i < 2; i++) {
        int idx = i * 512 + tid;
        int row = idx >> 3;
        int c   = idx & 7;
        CPA(dst + row * LDT + c * 16,
            (const char*)src + (size_t)row * ld_src * 2 + c * 16);
    }
}

// ---------------- GEMM1: persistent, fused gate+up + SwiGLU (plain fp16) ----------------
// stage: A BG BU -> 55296 B, 3 stages
#define G1_STAGE (3 * TILE)
#define G1_SMEM  (3 * G1_STAGE)
#define G1_NCH   (KDIM / 64)   // 32

__global__ __launch_bounds__(512, 1) void gemm1_kernel() {
    extern __shared__ char smem[];
    const uint32_t sb0 = smem_u32(smem);
    __shared__ int s_tile;

    const int tid  = threadIdx.x;
    const int w    = tid >> 5;
    const int lane = tid & 31;
    const int wm   = w & 3;
    const int wn   = w >> 2;
    const int lrow  = lane & 15;
    const int lkoff = (lane >> 4) * 16;
    const int ntile = g_n1;

    for (;;) {
        if (tid == 0) s_tile = atomicAdd(&g_ctr1, 1);
        __syncthreads();
        const int t = s_tile;
        if (t >= ntile) break;
        const int m   = g_map1[t];
        const int e   = m >> 16;
        const int c0  = ((m >> 8) & 0xFF) * 128;
        const int n0  = (m & 0xFF) * 128;
        const int cnt = g_counts[e];

        const __half* aT = g_a + ((size_t)e * CAP + c0) * KDIM;
        const __half* bG = g_gw + ((size_t)e * NDIM + n0) * KDIM;
        const __half* bU = g_uw + ((size_t)e * NDIM + n0) * KDIM;

        auto load_chunk = [&](int kc, int st) {
            uint32_t sb = sb0 + st * G1_STAGE;
            int ko = kc * 64;
            load_tile(sb + 0 * TILE, aT + ko, KDIM, tid);
            load_tile(sb + 1 * TILE, bG + ko, KDIM, tid);
            load_tile(sb + 2 * TILE, bU + ko, KDIM, tid);
            CPC();
        };

        float cg[2][4][4], cu[2][4][4];
#pragma unroll
        for (int tt = 0; tt < 2; tt++)
#pragma unroll
            for (int nt = 0; nt < 4; nt++)
#pragma unroll
                for (int j = 0; j < 4; j++) { cg[tt][nt][j] = 0.f; cu[tt][nt][j] = 0.f; }

        load_chunk(0, 0);
        load_chunk(1, 1);

        for (int c = 0; c < G1_NCH; c++) {
            const int s = c % 3;
            if (c + 2 < G1_NCH) { CPW1(); } else { CPW0(); }
            __syncthreads();
            if (c + 2 < G1_NCH) load_chunk(c + 2, (c + 2) % 3);

            const uint32_t sb = sb0 + s * G1_STAGE;
#pragma unroll
            for (int kk = 0; kk < 4; kk++) {
                const uint32_t kb = kk * 32 + lkoff;
                uint32_t ah[2][4];
#pragma unroll
                for (int tt = 0; tt < 2; tt++) {
                    uint32_t r = (wm * 32 + tt * 16 + lrow) * LDT + kb;
                    ldsm_x4(ah[tt], sb + r);
                }
                uint32_t bg[2][4], bu[2][4];
#pragma unroll
                for (int gix = 0; gix < 2; gix++) {
                    uint32_t r = (wn * 32 + gix * 16 + lrow) * LDT + kb;
                    ldsm_x4(bg[gix], sb + 1 * TILE + r);
                    ldsm_x4(bu[gix], sb + 2 * TILE + r);
                }
#pragma unroll
                for (int tt = 0; tt < 2; tt++)
#pragma unroll
                    for (int nt = 0; nt < 4; nt++) {
                        int gix = nt >> 1, sub = nt & 1;
                        mma16816(cg[tt][nt], ah[tt], bg[gix][sub], bg[gix][sub + 2]);
                        mma16816(cu[tt][nt], ah[tt], bu[gix][sub], bu[gix][sub + 2]);
                    }
            }
        }

        // epilogue: SwiGLU -> single fp16 h
#pragma unroll
        for (int tt = 0; tt < 2; tt++) {
#pragma unroll
            for (int jp = 0; jp < 2; jp++) {
                int crow = c0 + wm * 32 + tt * 16 + (lane >> 2) + jp * 8;
                if (crow >= cnt) continue;
                size_t rowbase = ((size_t)e * CAP + crow) * NDIM + n0 + wn * 32;
#pragma unroll
                for (int nt = 0; nt < 4; nt++) {
                    float g0 = fminf(cg[tt][nt][jp * 2],     10.0f);
                    float g1 = fminf(cg[tt][nt][jp * 2 + 1], 10.0f);
                    float u0 = fminf(fmaxf(cu[tt][nt][jp * 2],     -10.0f), 10.0f);
                    float u1 = fminf(fmaxf(cu[tt][nt][jp * 2 + 1], -10.0f), 10.0f);
                    float r0 = (g0 / (1.0f + __expf(-g0))) * u0;
                    float r1 = (g1 / (1.0f + __expf(-g1))) * u1;
                    int ncol = nt * 8 + (lane & 3) * 2;
                    *(__half2*)(g_h + rowbase + ncol) = __floats2half2_rn(r0, r1);
                }
            }
        }
    }
}

// ---------------- GEMM2: persistent, plain fp16 down projection ----------------
// stage: A B -> 36864 B, 3 stages (110 KB, 2 CTAs/SM attempt via regs? keep 2)
#define G2_STAGE (2 * TILE)
#define G2_SMEM  (3 * G2_STAGE)
#define G2_NCH   (NDIM / 64)   // 22

__global__ __launch_bounds__(512, 2) void gemm2_kernel() {
    extern __shared__ char smem[];
    const uint32_t sb0 = smem_u32(smem);
    __shared__ int s_tile;

    const int tid  = threadIdx.x;
    const int w    = tid >> 5;
    const int lane = tid & 31;
    const int wm   = w & 3;
    const int wn   = w >> 2;
    const int lrow  = lane & 15;
    const int lkoff = (lane >> 4) * 16;
    const int ntile = g_n2;

    for (;;) {
        if (tid == 0) s_tile = atomicAdd(&g_ctr2, 1);
        __syncthreads();
        const int t = s_tile;
        if (t >= ntile) break;
        const int m   = g_map2[t];
        const int e   = m >> 16;
        const int c0  = ((m >> 8) & 0xFF) * 128;
        const int k0  = (m & 0xFF) * 128;
        const int cnt = g_counts[e];

        const __half* aT = g_h + ((size_t)e * CAP + c0) * NDIM;
        const __half* bW = g_dw + ((size_t)e * KDIM + k0) * NDIM;

        auto load_chunk = [&](int kc, int st) {
            uint32_t sb = sb0 + st * G2_STAGE;
            int ko = kc * 64;
            load_tile(sb + 0 * TILE, aT + ko, NDIM, tid);
            load_tile(sb + 1 * TILE, bW + ko, NDIM, tid);
            CPC();
        };

        float acc[2][4][4];
#pragma unroll
        for (int tt = 0; tt < 2; tt++)
#pragma unroll
            for (int nt = 0; nt < 4; nt++)
#pragma unroll
                for (int j = 0; j < 4; j++) acc[tt][nt][j] = 0.f;

        load_chunk(0, 0);
        load_chunk(1, 1);

        for (int c = 0; c < G2_NCH; c++) {
            const int s = c % 3;
            if (c + 2 < G2_NCH) { CPW1(); } else { CPW0(); }
            __syncthreads();
            if (c + 2 < G2_NCH) load_chunk(c + 2, (c + 2) % 3);

            const uint32_t sb = sb0 + s * G2_STAGE;
#pragma unroll
            for (int kk = 0; kk < 4; kk++) {
                const uint32_t kb = kk * 32 + lkoff;
                uint32_t ah[2][4];
#pragma unroll
                for (int tt = 0; tt < 2; tt++) {
                    uint32_t r = (wm * 32 + tt * 16 + lrow) * LDT + kb;
                    ldsm_x4(ah[tt], sb + r);
                }
                uint32_t bh[2][4];
#pragma unroll
                for (int gix = 0; gix < 2; gix++) {
                    uint32_t r = (wn * 32 + gix * 16 + lrow) * LDT + kb;
                    ldsm_x4(bh[gix], sb + TILE + r);
                }
#pragma unroll
                for (int tt = 0; tt < 2; tt++)
#pragma unroll
                    for (int nt = 0; nt < 4; nt++) {
                        int gix = nt >> 1, sub = nt & 1;
                        mma16816(acc[tt][nt], ah[tt], bh[gix][sub], bh[gix][sub + 2]);
                    }
            }
        }

        // epilogue: fp32 store to g_d
#pragma unroll
        for (int tt = 0; tt < 2; tt++) {
#pragma unroll
            for (int jp = 0; jp < 2; jp++) {
                int crow = c0 + wm * 32 + tt * 16 + (lane >> 2) + jp * 8;
                if (crow >= cnt) continue;
                float* dst = g_d + ((size_t)e * CAP + crow) * KDIM + k0 + wn * 32;
#pragma unroll
                for (int nt = 0; nt < 4; nt++) {
                    float2 v;
                    v.x = acc[tt][nt][jp * 2];
                    v.y = acc[tt][nt][jp * 2 + 1];
                    *(float2*)(dst + nt * 8 + (lane & 3) * 2) = v;
                }
            }
        }
    }
}

// ---------------- combine ----------------
__global__ void combine_kernel(const int* __restrict__ idx,
                               const float* __restrict__ gate,
                               float* __restrict__ out)
{
    const int t = blockIdx.x;
    const int e0 = idx[2 * t], e1 = idx[2 * t + 1];
    const float w0 = gate[2 * t], w1 = gate[2 * t + 1];
    const int p0 = g_pos[2 * t], p1 = g_pos[2 * t + 1];
    const float* d0 = g_d + ((size_t)e0 * CAP + p0) * KDIM;
    const float* d1 = g_d + ((size_t)e1 * CAP + p1) * KDIM;
    float* o = out + (size_t)t * KDIM;

    for (int k = threadIdx.x * 4; k < KDIM; k += blockDim.x * 4) {
        float4 a = *(const float4*)(d0 + k);
        float4 b = *(const float4*)(d1 + k);
        float4 r;
        r.x = w0 * a.x + w1 * b.x;
        r.y = w0 * a.y + w1 * b.y;
        r.z = w0 * a.z + w1 * b.z;
        r.w = w0 * a.w + w1 * b.w;
        *(float4*)(o + k) = r;
    }
}

// ---------------- launch ----------------
extern "C" void kernel_launch(void* const* d_in, const int* in_sizes, int n_in,
                              void* d_out, int out_size)
{
    const float* X    = (const float*)d_in[0];
    const int*   idx  = (const int*)  d_in[1];
    const float* gate = (const float*)d_in[2];
    const float* GW   = (const float*)d_in[3];
    const float* UW   = (const float*)d_in[4];
    const float* DW   = (const float*)d_in[5];
    float* out = (float*)d_out;

    cudaFuncSetAttribute(gemm1_kernel, cudaFuncAttributeMaxDynamicSharedMemorySize, G1_SMEM);
    cudaFuncSetAttribute(gemm2_kernel, cudaFuncAttributeMaxDynamicSharedMemorySize, G2_SMEM);

    route_kernel<<<1, 256>>>(idx);
    convert_all_kernel<<<4096, 256>>>((const float4*)GW, (const float4*)UW,
                                      (const float4*)DW);
    dispatch_kernel<<<dim3(CAP, NE), 256>>>(X);

    gemm1_kernel<<<148, 512, G1_SMEM>>>();
    gemm2_kernel<<<296, 512, G2_SMEM>>>();

    combine_kernel<<<MTOK, 256>>>(idx, gate, out);
}

// round 16
// speedup vs baseline: 4.9768x; 1.0247x over previous
#include <cuda_runtime.h>
#include <cuda_fp16.h>
#include <math.h>
#include <stdint.h>

#define NE      8
#define TOPK    2
#define MTOK    2048
#define KDIM    2048
#define NDIM    1408
#define CAP     1024
#define RROWS   (MTOK * TOPK)

#define NB1 (NDIM / 64)    // 22
#define NB2 (KDIM / 128)   // 16

// ---------------- scratch (device globals; no allocations) ----------------
__device__ int   g_counts[NE];
__device__ int   g_tok[NE * CAP];
__device__ int   g_pos[RROWS];
__device__ int   g_map1[NE * (CAP / 128) * NB1];   // 1408 max
__device__ int   g_map2[NE * (CAP / 128) * NB2];   // 1024 max
__device__ int   g_n1, g_n2, g_ctr1, g_ctr2;
__device__ __half g_a[(size_t)NE * CAP * KDIM];
__device__ __half g_gw[(size_t)NE * NDIM * KDIM];
__device__ __half g_uw[(size_t)NE * NDIM * KDIM];
__device__ __half g_dw[(size_t)NE * KDIM * NDIM];
__device__ __half g_h[(size_t)NE * CAP * NDIM];
__device__ float g_d[(size_t)NE * CAP * KDIM];

// ---------------- helpers ----------------
__device__ __forceinline__ uint32_t smem_u32(const void* p) {
    return (uint32_t)__cvta_generic_to_shared(p);
}

#define CPA(dst, src) \
    asm volatile("cp.async.cg.shared.global [%0], [%1], 16;" :: "r"(dst), "l"(src) : "memory")
#define CPC()  asm volatile("cp.async.commit_group;" ::: "memory")
#define CPW1() asm volatile("cp.async.wait_group 1;" ::: "memory")
#define CPW0() asm volatile("cp.async.wait_group 0;" ::: "memory")

__device__ __forceinline__ void ldsm_x4(uint32_t* r, uint32_t a) {
    asm volatile("ldmatrix.sync.aligned.m8n8.x4.shared.b16 {%0,%1,%2,%3}, [%4];"
        : "=r"(r[0]), "=r"(r[1]), "=r"(r[2]), "=r"(r[3]) : "r"(a));
}

__device__ __forceinline__ void mma16816(float* c, const uint32_t* a,
                                         uint32_t b0, uint32_t b1) {
    asm volatile(
        "mma.sync.aligned.m16n8k16.row.col.f32.f16.f16.f32 "
        "{%0,%1,%2,%3}, {%4,%5,%6,%7}, {%8,%9}, {%0,%1,%2,%3};"
        : "+f"(c[0]), "+f"(c[1]), "+f"(c[2]), "+f"(c[3])
        : "r"(a[0]), "r"(a[1]), "r"(a[2]), "r"(a[3]), "r"(b0), "r"(b1));
}

#define LDT    144
#define TILEA  18432     // 128 rows * 144 B
#define TILEB  9216      // 64 rows * 144 B

// ---------------- routing + tile maps ----------------
__global__ void route_kernel(const int* __restrict__ idx) {
    __shared__ int scnt[NE];
    int tid = threadIdx.x;
    if (tid < NE) scnt[tid] = 0;
    __syncthreads();
    for (int r = tid; r < RROWS; r += blockDim.x) {
        int e = idx[r];
        int p = atomicAdd(&scnt[e], 1);
        g_pos[r] = p;
        if (p < CAP) g_tok[e * CAP + p] = r >> 1;
    }
    __syncthreads();
    if (tid < NE) g_counts[tid] = scnt[tid];
    if (tid == 0) {
        int n1 = 0, n2 = 0;
        for (int e = 0; e < NE; e++) {
            int nb = (scnt[e] + 127) >> 7;
            for (int cb = 0; cb < nb; cb++) {
                for (int x = 0; x < NB1; x++)
                    g_map1[n1++] = (e << 16) | (cb << 8) | x;
                for (int x = 0; x < NB2; x++)
                    g_map2[n2++] = (e << 16) | (cb << 8) | x;
            }
        }
        g_n1 = n1; g_n2 = n2;
        g_ctr1 = 0; g_ctr2 = 0;
    }
}

// ---------------- fused weight conversion ----------------
#define WQ ((NE * NDIM * KDIM) / 4)
__global__ void convert_all_kernel(const float4* __restrict__ GW,
                                   const float4* __restrict__ UW,
                                   const float4* __restrict__ DW) {
    for (int i = blockIdx.x * blockDim.x + threadIdx.x; i < 3 * WQ;
         i += gridDim.x * blockDim.x) {
        const float4* s;
        __half2* dh;
        int j;
        if (i < WQ)          { j = i;          s = GW; dh = (__half2*)g_gw; }
        else if (i < 2 * WQ) { j = i - WQ;     s = UW; dh = (__half2*)g_uw; }
        else                 { j = i - 2 * WQ; s = DW; dh = (__half2*)g_dw; }
        float4 v = s[j];
        dh[2 * j]     = __halves2half2(__float2half_rn(v.x), __float2half_rn(v.y));
        dh[2 * j + 1] = __halves2half2(__float2half_rn(v.z), __float2half_rn(v.w));
    }
}

// ---------------- dispatch ----------------
__global__ void dispatch_kernel(const float* __restrict__ X) {
    int e = blockIdx.y, slot = blockIdx.x;
    if (slot >= g_counts[e]) return;
    int tok = g_tok[e * CAP + slot];
    const float4* src = (const float4*)(X + (size_t)tok * KDIM);
    __half2* dh = (__half2*)(g_a + ((size_t)e * CAP + slot) * KDIM);
    for (int q = threadIdx.x; q < KDIM / 4; q += blockDim.x) {
        float4 v = src[q];
        dh[2 * q]     = __floats2half2_rn(v.x, v.y);
        dh[2 * q + 1] = __floats2half2_rn(v.z, v.w);
    }
}

// ---------------- tile loaders (256 threads) ----------------
template <int R>
__device__ __forceinline__ void load_tile(uint32_t dst, const __half* src,
                                          int ld_src, int tid) {
#pragma unroll
    for (int i = 0; i < (R * 8) / 256; i++) {
        int idx = i * 256 + tid;
        int row = idx >> 3;
        int c   = idx & 7;
        CPA(dst + row * LDT + c * 16,
            (const char*)src + (size_t)row * ld_src * 2 + c * 16);
    }
}

// ---------------- GEMM1: persistent, 128x64 CTA tile, 2 CTAs/SM ----------------
// stage: A(128) BG(64) BU(64) -> 36864 B, 3 stages = 110592 B
#define G1_STAGE (TILEA + 2 * TILEB)
#define G1_SMEM  (3 * G1_STAGE)
#define G1_NCH   (KDIM / 64)   // 32

__global__ __launch_bounds__(256, 2) void gemm1_kernel() {
    extern __shared__ char smem[];
    const uint32_t sb0 = smem_u32(smem);
    __shared__ int s_tile;

    const int tid  = threadIdx.x;
    const int w    = tid >> 5;
    const int lane = tid & 31;
    const int wm   = w & 3;      // 32-row band (0..3)
    const int wn   = w >> 2;     // 32-col group (0..1)
    const int lrow  = lane & 15;
    const int lkoff = (lane >> 4) * 16;
    const int ntile = g_n1;

    for (;;) {
        if (tid == 0) s_tile = atomicAdd(&g_ctr1, 1);
        __syncthreads();
        const int t = s_tile;
        if (t >= ntile) break;
        const int m   = g_map1[t];
        const int e   = m >> 16;
        const int c0  = ((m >> 8) & 0xFF) * 128;
        const int n0  = (m & 0xFF) * 64;
        const int cnt = g_counts[e];

        const __half* aT = g_a + ((size_t)e * CAP + c0) * KDIM;
        const __half* bG = g_gw + ((size_t)e * NDIM + n0) * KDIM;
        const __half* bU = g_uw + ((size_t)e * NDIM + n0) * KDIM;

        auto load_chunk = [&](int kc, int st) {
            uint32_t sb = sb0 + st * G1_STAGE;
            int ko = kc * 64;
            load_tile<128>(sb, aT + ko, KDIM, tid);
            load_tile<64>(sb + TILEA, bG + ko, KDIM, tid);
            load_tile<64>(sb + TILEA + TILEB, bU + ko, KDIM, tid);
            CPC();
        };

        float cg[2][4][4], cu[2][4][4];
#pragma unroll
        for (int tt = 0; tt < 2; tt++)
#pragma unroll
            for (int nt = 0; nt < 4; nt++)
#pragma unroll
                for (int j = 0; j < 4; j++) { cg[tt][nt][j] = 0.f; cu[tt][nt][j] = 0.f; }

        load_chunk(0, 0);
        load_chunk(1, 1);

        for (int c = 0; c < G1_NCH; c++) {
            const int s = c % 3;
            if (c + 2 < G1_NCH) { CPW1(); } else { CPW0(); }
            __syncthreads();
            if (c + 2 < G1_NCH) load_chunk(c + 2, (c + 2) % 3);

            const uint32_t sb = sb0 + s * G1_STAGE;
#pragma unroll
            for (int kk = 0; kk < 4; kk++) {
                const uint32_t kb = kk * 32 + lkoff;
                uint32_t ah[2][4];
#pragma unroll
                for (int tt = 0; tt < 2; tt++) {
                    uint32_t r = (wm * 32 + tt * 16 + lrow) * LDT + kb;
                    ldsm_x4(ah[tt], sb + r);
                }
                uint32_t bg[2][4], bu[2][4];
#pragma unroll
                for (int gix = 0; gix < 2; gix++) {
                    uint32_t r = (wn * 32 + gix * 16 + lrow) * LDT + kb;
                    ldsm_x4(bg[gix], sb + TILEA + r);
                    ldsm_x4(bu[gix], sb + TILEA + TILEB + r);
                }
#pragma unroll
                for (int tt = 0; tt < 2; tt++)
#pragma unroll
                    for (int nt = 0; nt < 4; nt++) {
                        int gix = nt >> 1, sub = nt & 1;
                        mma16816(cg[tt][nt], ah[tt], bg[gix][sub], bg[gix][sub + 2]);
                        mma16816(cu[tt][nt], ah[tt], bu[gix][sub], bu[gix][sub + 2]);
                    }
            }
        }

        // epilogue: SwiGLU -> fp16 h
#pragma unroll
        for (int tt = 0; tt < 2; tt++) {
#pragma unroll
            for (int jp = 0; jp < 2; jp++) {
                int crow = c0 + wm * 32 + tt * 16 + (lane >> 2) + jp * 8;
                if (crow >= cnt) continue;
                size_t rowbase = ((size_t)e * CAP + crow) * NDIM + n0 + wn * 32;
#pragma unroll
                for (int nt = 0; nt < 4; nt++) {
                    float g0 = fminf(cg[tt][nt][jp * 2],     10.0f);
                    float g1 = fminf(cg[tt][nt][jp * 2 + 1], 10.0f);
                    float u0 = fminf(fmaxf(cu[tt][nt][jp * 2],     -10.0f), 10.0f);
                    float u1 = fminf(fmaxf(cu[tt][nt][jp * 2 + 1], -10.0f), 10.0f);
                    float r0 = (g0 / (1.0f + __expf(-g0))) * u0;
                    float r1 = (g1 / (1.0f + __expf(-g1))) * u1;
                    int ncol = nt * 8 + (lane & 3) * 2;
                    *(__half2*)(g_h + rowbase + ncol) = __floats2half2_rn(r0, r1);
                }
            }
        }
    }
}

// ---------------- GEMM2: persistent, 128x128 CTA tile, 256 thr, 2 CTAs/SM ----------------
// stage: A(128) B(128) -> 36864 B, 3 stages = 110592 B
#define G2_STAGE (2 * TILEA)
#define G2_SMEM  (3 * G2_STAGE)
#define G2_NCH   (NDIM / 64)   // 22

__global__ __launch_bounds__(256, 2) void gemm2_kernel() {
    extern __shared__ char smem[];
    const uint32_t sb0 = smem_u32(smem);
    __shared__ int s_tile;

    const int tid  = threadIdx.x;
    const int w    = tid >> 5;
    const int lane = tid & 31;
    const int wm   = w & 3;      // 32-row band (0..3)
    const int wn   = w >> 2;     // 64-col group (0..1)
    const int lrow  = lane & 15;
    const int lkoff = (lane >> 4) * 16;
    const int ntile = g_n2;

    for (;;) {
        if (tid == 0) s_tile = atomicAdd(&g_ctr2, 1);
        __syncthreads();
        const int t = s_tile;
        if (t >= ntile) break;
        const int m   = g_map2[t];
        const int e   = m >> 16;
        const int c0  = ((m >> 8) & 0xFF) * 128;
        const int k0  = (m & 0xFF) * 128;
        const int cnt = g_counts[e];

        const __half* aT = g_h + ((size_t)e * CAP + c0) * NDIM;
        const __half* bW = g_dw + ((size_t)e * KDIM + k0) * NDIM;

        auto load_chunk = [&](int kc, int st) {
            uint32_t sb = sb0 + st * G2_STAGE;
            int ko = kc * 64;
            load_tile<128>(sb, aT + ko, NDIM, tid);
            load_tile<128>(sb + TILEA, bW + ko, NDIM, tid);
            CPC();
        };

        float acc[2][8][4];
#pragma unroll
        for (int tt = 0; tt < 2; tt++)
#pragma unroll
            for (int nt = 0; nt < 8; nt++)
#pragma unroll
                for (int j = 0; j < 4; j++) acc[tt][nt][j] = 0.f;

        load_chunk(0, 0);
        load_chunk(1, 1);

        for (int c = 0; c < G2_NCH; c++) {
            const int s = c % 3;
            if (c + 2 < G2_NCH) { CPW1(); } else { CPW0(); }
            __syncthreads();
            if (c + 2 < G2_NCH) load_chunk(c + 2, (c + 2) % 3);

            const uint32_t sb = sb0 + s * G2_STAGE;
#pragma unroll
            for (int kk = 0; kk < 4; kk++) {
                const uint32_t kb = kk * 32 + lkoff;
                uint32_t ah[2][4];
#pragma unroll
                for (int tt = 0; tt < 2; tt++) {
                    uint32_t r = (wm * 32 + tt * 16 + lrow) * LDT + kb;
                    ldsm_x4(ah[tt], sb + r);
                }
                uint32_t bh[4][4];
#pragma unroll
                for (int gix = 0; gix < 4; gix++) {
                    uint32_t r = (wn * 64 + gix * 16 + lrow) * LDT + kb;
                    ldsm_x4(bh[gix], sb + TILEA + r);
                }
#pragma unroll
                for (int tt = 0; tt < 2; tt++)
#pragma unroll
                    for (int nt = 0; nt < 8; nt++) {
                        int gix = nt >> 1, sub = nt & 1;
                        mma16816(acc[tt][nt], ah[tt], bh[gix][sub], bh[gix][sub + 2]);
                    }
            }
        }

        // epilogue: fp32 store to g_d
#pragma unroll
        for (int tt = 0; tt < 2; tt++) {
#pragma unroll
            for (int jp = 0; jp < 2; jp++) {
                int crow = c0 + wm * 32 + tt * 16 + (lane >> 2) + jp * 8;
                if (crow >= cnt) continue;
                float* dst = g_d + ((size_t)e * CAP + crow) * KDIM + k0 + wn * 64;
#pragma unroll
                for (int nt = 0; nt < 8; nt++) {
                    float2 v;
                    v.x = acc[tt][nt][jp * 2];
                    v.y = acc[tt][nt][jp * 2 + 1];
                    *(float2*)(dst + nt * 8 + (lane & 3) * 2) = v;
                }
            }
        }
    }
}

// ---------------- combine ----------------
__global__ void combine_kernel(const int* __restrict__ idx,
                               const float* __restrict__ gate,
                               float* __restrict__ out)
{
    const int t = blockIdx.x;
    const int e0 = idx[2 * t], e1 = idx[2 * t + 1];
    const float w0 = gate[2 * t], w1 = gate[2 * t + 1];
    const int p0 = g_pos[2 * t], p1 = g_pos[2 * t + 1];
    const float* d0 = g_d + ((size_t)e0 * CAP + p0) * KDIM;
    const float* d1 = g_d + ((size_t)e1 * CAP + p1) * KDIM;
    float* o = out + (size_t)t * KDIM;

    for (int k = threadIdx.x * 4; k < KDIM; k += blockDim.x * 4) {
        float4 a = *(const float4*)(d0 + k);
        float4 b = *(const float4*)(d1 + k);
        float4 r;
        r.x = w0 * a.x + w1 * b.x;
        r.y = w0 * a.y + w1 * b.y;
        r.z = w0 * a.z + w1 * b.z;
        r.w = w0 * a.w + w1 * b.w;
        *(float4*)(o + k) = r;
    }
}

// ---------------- launch ----------------
extern "C" void kernel_launch(void* const* d_in, const int* in_sizes, int n_in,
                              void* d_out, int out_size)
{
    const float* X    = (const float*)d_in[0];
    const int*   idx  = (const int*)  d_in[1];
    const float* gate = (const float*)d_in[2];
    const float* GW   = (const float*)d_in[3];
    const float* UW   = (const float*)d_in[4];
    const float* DW   = (const float*)d_in[5];
    float* out = (float*)d_out;

    cudaFuncSetAttribute(gemm1_kernel, cudaFuncAttributeMaxDynamicSharedMemorySize, G1_SMEM);
    cudaFuncSetAttribute(gemm2_kernel, cudaFuncAttributeMaxDynamicSharedMemorySize, G2_SMEM);

    route_kernel<<<1, 256>>>(idx);
    convert_all_kernel<<<4096, 256>>>((const float4*)GW, (const float4*)UW,
                                      (const float4*)DW);
    dispatch_kernel<<<dim3(CAP, NE), 256>>>(X);

    gemm1_kernel<<<296, 256, G1_SMEM>>>();
    gemm2_kernel<<<296, 256, G2_SMEM>>>();

    combine_kernel<<<MTOK, 256>>>(idx, gate, out);
}